// round 5
// baseline (speedup 1.0000x reference)
#include <cuda_runtime.h>
#include <math_constants.h>

#define NQ     4096
#define NKV    32768
#define CDIM   256
#define KNN    100
#define NSPLIT 4
#define RANGE  (NKV / NSPLIT)     // 8192
#define TILE   2048
#define LCAP   64                 // per-lane slot cap within a (query,split) segment
#define SEGSZ  (LCAP * 32)        // 2048 entries per (query,split)
#define QPW    4
#define WPB    4
#define FW     8                  // warps per block in knn_final
#define FULLM  0xffffffffu

// ---------------- static scratch ----------------
__device__ uint2 g_buf[(size_t)NQ * NSPLIT * SEGSZ]; // {d2 bits (>=0), kv idx}
__device__ int   g_cntl[NQ * NSPLIT * 32];           // per-lane counts
__device__ int   g_topk[(size_t)NQ * KNN];

// ---------------- helpers ----------------
__device__ __forceinline__ int warp_sum_i(int v) {
#pragma unroll
    for (int o = 16; o; o >>= 1) v += __shfl_xor_sync(FULLM, v, o);
    return v;
}
__device__ __forceinline__ float warp_sum_f(float v) {
#pragma unroll
    for (int o = 16; o; o >>= 1) v += __shfl_xor_sync(FULLM, v, o);
    return v;
}
__device__ __forceinline__ float warp_max_f(float v) {
#pragma unroll
    for (int o = 16; o; o >>= 1) v = fmaxf(v, __shfl_xor_sync(FULLM, v, o));
    return v;
}
__device__ __forceinline__ int warp_min_i(int v) {
#pragma unroll
    for (int o = 16; o; o >>= 1) v = min(v, __shfl_xor_sync(FULLM, v, o));
    return v;
}
__device__ __forceinline__ int warp_max_i(int v) {
#pragma unroll
    for (int o = 16; o; o >>= 1) v = max(v, __shfl_xor_sync(FULLM, v, o));
    return v;
}

// ================= kernel 1: candidate scan (KV-split, lane-private slots) ==
// grid = (NQ/16, NSPLIT). Warp: 4 queries over one 8192-wide KV range.
// Sample (first 2048 of range) -> per-lane sorted-4 stash -> safe threshold
// (>= split-sample 100th >= split 100th >= global 100th). Admits go to the
// lane's private column of the (q,split) segment: NO ballots, NO atomics.
__global__ void __launch_bounds__(32 * WPB) knn_scan(
    const float* __restrict__ qpos, const float* __restrict__ kpos)
{
    __shared__ float4 s_tile[TILE];

    const int tid = threadIdx.x, lane = tid & 31, warp = tid >> 5;
    const int qbase = blockIdx.x * (WPB * QPW) + warp * QPW;
    const int split = blockIdx.y;
    const int kbase = split * RANGE;

    float ax[QPW], ay[QPW], az[QPW], c0[QPW], thr[QPW];
    int cnt[QPW];
#pragma unroll
    for (int j = 0; j < QPW; j++) {
        int q = qbase + j;
        float qx = qpos[3 * q], qy = qpos[3 * q + 1], qz = qpos[3 * q + 2];
        c0[j] = fmaf(qx, qx, fmaf(qy, qy, qz * qz));
        ax[j] = -2.f * qx; ay[j] = -2.f * qy; az[j] = -2.f * qz;
        cnt[j] = 0;
    }

    // ---- load tile A (first 2048 of range) ----
    for (int i = tid; i < TILE; i += 32 * WPB) {
        int g = kbase + i;
        float x = kpos[3 * g], y = kpos[3 * g + 1], z = kpos[3 * g + 2];
        s_tile[i] = make_float4(x, y, z, fmaf(x, x, fmaf(y, y, z * z)));
    }
    __syncthreads();

    // ---- sample phase: per-lane sorted-4 minima, threshold = kth of 128 stash
    {
        float m[QPW][4];
#pragma unroll
        for (int j = 0; j < QPW; j++)
#pragma unroll
            for (int s = 0; s < 4; s++) m[j][s] = CUDART_INF_F;

        for (int i = lane; i < TILE; i += 32) {
            float4 kp = s_tile[i];
#pragma unroll
            for (int j = 0; j < QPW; j++) {
                float d = fmaf(ax[j], kp.x, c0[j] + kp.w);
                d = fmaf(ay[j], kp.y, d);
                d = fmaf(az[j], kp.z, d);
                d = fmaxf(d, 0.f);
                float t0 = fminf(m[j][0], d), t1 = fmaxf(m[j][0], d); m[j][0] = t0;
                float t2 = fminf(m[j][1], t1), t3 = fmaxf(m[j][1], t1); m[j][1] = t2;
                float t4 = fminf(m[j][2], t3), t5 = fmaxf(m[j][2], t3); m[j][2] = t4;
                m[j][3] = fminf(m[j][3], t5);
            }
        }
#pragma unroll
        for (int j = 0; j < QPW; j++) {
            unsigned lo = 0u, hi = 0x7f800000u;
#pragma unroll
            for (int it = 0; it < 16; it++) {
                unsigned mid = lo + ((hi - lo) >> 1);
                int c = 0;
#pragma unroll
                for (int s = 0; s < 4; s++) c += (__float_as_uint(m[j][s]) <= mid) ? 1 : 0;
                c = warp_sum_i(c);
                if (c >= KNN) hi = mid; else lo = mid + 1u;
            }
            thr[j] = __uint_as_float(hi);
        }
    }

    uint2* seg[QPW];
#pragma unroll
    for (int j = 0; j < QPW; j++)
        seg[j] = g_buf + ((size_t)(qbase + j) * NSPLIT + split) * SEGSZ;

    // ---- main scan ----
    for (int t0 = 0; t0 < RANGE; t0 += TILE) {
        if (t0) {
            __syncthreads();
            for (int i = tid; i < TILE; i += 32 * WPB) {
                int g = kbase + t0 + i;
                float x = kpos[3 * g], y = kpos[3 * g + 1], z = kpos[3 * g + 2];
                s_tile[i] = make_float4(x, y, z, fmaf(x, x, fmaf(y, y, z * z)));
            }
            __syncthreads();
        }
        for (int i = lane; i < TILE; i += 32) {
            float4 kp = s_tile[i];
#pragma unroll
            for (int j = 0; j < QPW; j++) {
                float d = fmaf(ax[j], kp.x, c0[j] + kp.w);
                d = fmaf(ay[j], kp.y, d);
                d = fmaf(az[j], kp.z, d);
                if (d <= thr[j]) {
                    int c = cnt[j];
                    if (c < LCAP)
                        seg[j][(c << 5) + lane] =
                            make_uint2(__float_as_uint(fmaxf(d, 0.f)),
                                       (unsigned)(kbase + t0 + i));
                    cnt[j] = c + 1;
                }
            }
        }
    }
#pragma unroll
    for (int j = 0; j < QPW; j++)
        g_cntl[((qbase + j) * NSPLIT + split) * 32 + lane] = min(cnt[j], LCAP);
}

// ================= kernel 2: exact top-100 via 8-bit radix select ===========
// Warp per query, 8 warps/block. Reads segments straight from L2 (per-lane
// columns are coalesced). Histograms use match-aggregated smem atomics.
__global__ void __launch_bounds__(32 * FW) knn_final()
{
    __shared__ int s_hist[FW][257];
    __shared__ int s_tie[FW][64];
    __shared__ int s_ctr[FW][2];

    const int lane = threadIdx.x & 31, w = threadIdx.x >> 5;
    const int q = blockIdx.x * FW + w;

    const uint2* seg[NSPLIT];
    int c[NSPLIT], mc[NSPLIT];
#pragma unroll
    for (int s = 0; s < NSPLIT; s++) {
        seg[s] = g_buf + ((size_t)q * NSPLIT + s) * SEGSZ;
        c[s] = g_cntl[(q * NSPLIT + s) * 32 + lane];
        mc[s] = warp_max_i(c[s]);
    }

    // ---- 4-round radix select: exact bits of the 100th smallest value ----
    unsigned prefix = 0;
    int kk = KNN;
#pragma unroll
    for (int shift = 24; shift >= 0; shift -= 8) {
        for (int b = lane; b < 256; b += 32) s_hist[w][b] = 0;
        __syncwarp();
        const unsigned himask = (shift == 24) ? 0u : ~((1u << (shift + 8)) - 1u);
#pragma unroll
        for (int s = 0; s < NSPLIT; s++) {
            for (int i = 0; i < mc[s]; i++) {
                bool valid = (i < c[s]);
                unsigned bits = valid ? seg[s][(i << 5) + lane].x : 0u;
                valid = valid && ((bits & himask) == prefix);
                unsigned act = __ballot_sync(FULLM, valid);
                if (valid) {
                    int bin = (bits >> shift) & 0xFF;
                    unsigned peers = __match_any_sync(act, bin);
                    if ((int)__ffs(peers) - 1 == lane)
                        atomicAdd(&s_hist[w][bin], __popc(peers));
                }
            }
        }
        __syncwarp();
        // scan 256 bins (lane owns 8 consecutive)
        int loc[8], sum = 0;
#pragma unroll
        for (int t = 0; t < 8; t++) { loc[t] = sum; sum += s_hist[w][lane * 8 + t]; }
        int ex = sum;
#pragma unroll
        for (int o = 1; o < 32; o <<= 1) {
            int tv = __shfl_up_sync(FULLM, ex, o);
            if (lane >= o) ex += tv;
        }
        ex -= sum;   // exclusive prefix of lane's bin-group
        int found = 999, cbf = 0;
#pragma unroll
        for (int t = 0; t < 8; t++) {
            int cb = ex + loc[t], ct = s_hist[w][lane * 8 + t];
            if (found == 999 && kk > cb && kk <= cb + ct) { found = lane * 8 + t; cbf = cb; }
        }
        int mf = warp_min_i(found);
        unsigned who = __ballot_sync(FULLM, found == mf);
        cbf = __shfl_sync(FULLM, cbf, __ffs(who) - 1);
        prefix |= ((unsigned)mf) << shift;
        kk -= cbf;
        __syncwarp();
    }
    const unsigned Tb = prefix;

    // ---- emit: all < Tb, then ties == Tb resolved to smallest kv indices ----
    if (lane == 0) { s_ctr[w][0] = 0; s_ctr[w][1] = 0; }
    __syncwarp();
    int* out = g_topk + (size_t)q * KNN;
#pragma unroll
    for (int s = 0; s < NSPLIT; s++) {
        for (int i = 0; i < mc[s]; i++) {
            bool valid = (i < c[s]);
            uint2 e = valid ? seg[s][(i << 5) + lane] : make_uint2(0xffffffffu, 0u);
            if (valid && e.x < Tb) {
                out[atomicAdd(&s_ctr[w][0], 1)] = (int)e.y;
            } else if (valid && e.x == Tb) {
                int p = atomicAdd(&s_ctr[w][1], 1);
                if (p < 64) s_tie[w][p] = (int)e.y;
            }
        }
    }
    __syncwarp();
    const int nout = s_ctr[w][0];
    const int tc = min(s_ctr[w][1], 64);
    const int need = KNN - nout;
    for (int r = 0; r < need; r++) {
        int v0 = (lane < tc) ? s_tie[w][lane] : 0x7fffffff;
        int v1 = (lane + 32 < tc) ? s_tie[w][lane + 32] : 0x7fffffff;
        int mv = warp_min_i(min(v0, v1));
        if (v0 == mv && lane < tc) s_tie[w][lane] = 0x7fffffff;
        else if (v1 == mv && lane + 32 < tc) s_tie[w][lane + 32] = 0x7fffffff;
        if (lane == 0) out[nout + r] = mv;
        __syncwarp();
    }
}

// ================= kernel 3: gather attention + residual(2x) + LN ==========
__global__ void __launch_bounds__(CDIM) attn_ln(
    const float* __restrict__ qf, const float* __restrict__ kf,
    const float* __restrict__ vf, const float* __restrict__ gamma,
    const float* __restrict__ beta, float* __restrict__ out)
{
    const int q = blockIdx.x;
    const int tid = threadIdx.x, lane = tid & 31, warp = tid >> 5;

    __shared__ int    s_idx[KNN];
    __shared__ float  s_logit[KNN];
    __shared__ float  s_p[KNN];
    __shared__ float4 s_part[3][64];
    __shared__ float4 s_x4[64];
    __shared__ float  s_red[8];
    __shared__ float  s_mean, s_rstd, s_inv;

    if (tid < KNN) s_idx[tid] = g_topk[(size_t)q * KNN + tid];

    const float4* qf4 = (const float4*)(qf + (size_t)q * CDIM);
    const float4  qa = qf4[lane], qb = qf4[32 + lane];
    __syncthreads();

    // QK^T: two neighbors per reduction round
    for (int n = warp; n < KNN; n += 16) {
        const int n2 = n + 8;
        const bool has2 = (n2 < KNN);
        const float4* kr1 = (const float4*)(kf + (size_t)s_idx[n] * CDIM);
        const float4* kr2 = (const float4*)(kf + (size_t)s_idx[has2 ? n2 : n] * CDIM);
        float4 ka1 = kr1[lane], kb1 = kr1[32 + lane];
        float4 ka2 = kr2[lane], kb2 = kr2[32 + lane];
        float s1 = qa.x * ka1.x, s2 = qa.x * ka2.x;
        s1 = fmaf(qa.y, ka1.y, s1);  s2 = fmaf(qa.y, ka2.y, s2);
        s1 = fmaf(qa.z, ka1.z, s1);  s2 = fmaf(qa.z, ka2.z, s2);
        s1 = fmaf(qa.w, ka1.w, s1);  s2 = fmaf(qa.w, ka2.w, s2);
        s1 = fmaf(qb.x, kb1.x, s1);  s2 = fmaf(qb.x, kb2.x, s2);
        s1 = fmaf(qb.y, kb1.y, s1);  s2 = fmaf(qb.y, kb2.y, s2);
        s1 = fmaf(qb.z, kb1.z, s1);  s2 = fmaf(qb.z, kb2.z, s2);
        s1 = fmaf(qb.w, kb1.w, s1);  s2 = fmaf(qb.w, kb2.w, s2);
#pragma unroll
        for (int o = 16; o; o >>= 1) {
            s1 += __shfl_xor_sync(FULLM, s1, o);
            s2 += __shfl_xor_sync(FULLM, s2, o);
        }
        if (lane == 0) {
            s_logit[n] = s1 * 0.0625f;                 // C^-0.5 = 1/16
            if (has2) s_logit[n2] = s2 * 0.0625f;
        }
    }
    __syncthreads();

    // softmax (warp 0)
    if (warp == 0) {
        float mx = -CUDART_INF_F;
        for (int i = lane; i < KNN; i += 32) mx = fmaxf(mx, s_logit[i]);
        mx = warp_max_f(mx);
        float sm = 0.f;
        for (int i = lane; i < KNN; i += 32) {
            float e = __expf(s_logit[i] - mx);
            s_p[i] = e; sm += e;
        }
        sm = warp_sum_f(sm);
        if (lane == 0) s_inv = 1.f / sm;
    }
    __syncthreads();

    // PV: 4 neighbor-groups x 64 float4 channel slots, dual accumulators
    const int g = warp >> 1;
    const int col = (warp & 1) * 32 + lane;
    float4 a0 = make_float4(0.f, 0.f, 0.f, 0.f);
    float4 a1 = make_float4(0.f, 0.f, 0.f, 0.f);
    int n = g;
#pragma unroll 3
    for (; n + 4 < KNN; n += 8) {
        const float4 v0 = ((const float4*)(vf + (size_t)s_idx[n] * CDIM))[col];
        const float4 v1 = ((const float4*)(vf + (size_t)s_idx[n + 4] * CDIM))[col];
        const float p0 = s_p[n], p1 = s_p[n + 4];
        a0.x = fmaf(p0, v0.x, a0.x);  a1.x = fmaf(p1, v1.x, a1.x);
        a0.y = fmaf(p0, v0.y, a0.y);  a1.y = fmaf(p1, v1.y, a1.y);
        a0.z = fmaf(p0, v0.z, a0.z);  a1.z = fmaf(p1, v1.z, a1.z);
        a0.w = fmaf(p0, v0.w, a0.w);  a1.w = fmaf(p1, v1.w, a1.w);
    }
    if (n < KNN) {
        const float4 v0 = ((const float4*)(vf + (size_t)s_idx[n] * CDIM))[col];
        const float p0 = s_p[n];
        a0.x = fmaf(p0, v0.x, a0.x);
        a0.y = fmaf(p0, v0.y, a0.y);
        a0.z = fmaf(p0, v0.z, a0.z);
        a0.w = fmaf(p0, v0.w, a0.w);
    }
    float4 acc = make_float4(a0.x + a1.x, a0.y + a1.y, a0.z + a1.z, a0.w + a1.w);
    if (g) s_part[g - 1][col] = acc;
    __syncthreads();
    if (g == 0) {
        float4 a = s_part[0][col], b = s_part[1][col], c = s_part[2][col];
        float sc = 2.f * s_inv;                        // res fully overwritten: y = 2x
        s_x4[col] = make_float4((acc.x + a.x + b.x + c.x) * sc,
                                (acc.y + a.y + b.y + c.y) * sc,
                                (acc.z + a.z + b.z + c.z) * sc,
                                (acc.w + a.w + b.w + c.w) * sc);
    }
    __syncthreads();

    // LayerNorm over CDIM
    float y = ((const float*)s_x4)[tid];
    float s = warp_sum_f(y);
    if (lane == 0) s_red[warp] = s;
    __syncthreads();
    if (warp == 0) {
        float v = (lane < 8) ? s_red[lane] : 0.f;
        v = warp_sum_f(v);
        if (lane == 0) s_mean = v * (1.f / CDIM);
    }
    __syncthreads();
    float d = y - s_mean;
    float s2 = warp_sum_f(d * d);
    if (lane == 0) s_red[warp] = s2;
    __syncthreads();
    if (warp == 0) {
        float v = (lane < 8) ? s_red[lane] : 0.f;
        v = warp_sum_f(v);
        if (lane == 0) s_rstd = rsqrtf(v * (1.f / CDIM) + 1e-5f);
    }
    __syncthreads();

    out[(size_t)q * CDIM + tid] = d * s_rstd * gamma[tid] + beta[tid];
}

// ---------------- launch ----------------
extern "C" void kernel_launch(void* const* d_in, const int* in_sizes, int n_in,
                              void* d_out, int out_size) {
    (void)in_sizes; (void)n_in; (void)out_size;
    const float* qf    = (const float*)d_in[1];
    const float* kf    = (const float*)d_in[2];
    const float* vf    = (const float*)d_in[3];
    const float* qpos  = (const float*)d_in[4];
    const float* kpos  = (const float*)d_in[5];
    const float* gamma = (const float*)d_in[6];
    const float* beta  = (const float*)d_in[7];

    knn_scan<<<dim3(NQ / (WPB * QPW), NSPLIT), 32 * WPB>>>(qpos, kpos);
    knn_final<<<NQ / FW, 32 * FW>>>();
    attn_ln<<<NQ, CDIM>>>(qf, kf, vf, gamma, beta, (float*)d_out);
}

// round 6
// speedup vs baseline: 1.4399x; 1.4399x over previous
#include <cuda_runtime.h>
#include <math_constants.h>

#define NQ     4096
#define NKV    32768
#define CDIM   256
#define KNN    100
#define NSPLIT 4
#define RANGE  (NKV / NSPLIT)     // 8192
#define TILE   2048
#define CAPS   1024               // per (query,split) segment capacity
#define QPW    4
#define WPB    4
#define FW     8                  // warps per block in knn_final
#define FULLM  0xffffffffu

// ---------------- static scratch ----------------
__device__ uint2 g_buf[(size_t)NQ * NSPLIT * CAPS];  // {d2 bits (>=0), kv idx}
__device__ int   g_cnt[NQ * NSPLIT];
__device__ int   g_topk[(size_t)NQ * KNN];

// ---------------- helpers ----------------
__device__ __forceinline__ int warp_sum_i(int v) {
#pragma unroll
    for (int o = 16; o; o >>= 1) v += __shfl_xor_sync(FULLM, v, o);
    return v;
}
__device__ __forceinline__ float warp_sum_f(float v) {
#pragma unroll
    for (int o = 16; o; o >>= 1) v += __shfl_xor_sync(FULLM, v, o);
    return v;
}
__device__ __forceinline__ float warp_max_f(float v) {
#pragma unroll
    for (int o = 16; o; o >>= 1) v = fmaxf(v, __shfl_xor_sync(FULLM, v, o));
    return v;
}
__device__ __forceinline__ int warp_min_i(int v) {
#pragma unroll
    for (int o = 16; o; o >>= 1) v = min(v, __shfl_xor_sync(FULLM, v, o));
    return v;
}

// ================= kernel 1: candidate scan (KV-split) =================
// PROVEN 127us version (R4): ballot append -> packed, coalesced segment writes.
__global__ void __launch_bounds__(32 * WPB) knn_scan(
    const float* __restrict__ qpos, const float* __restrict__ kpos)
{
    __shared__ float4 s_tile[TILE];

    const int tid = threadIdx.x, lane = tid & 31, warp = tid >> 5;
    const int qbase = blockIdx.x * (WPB * QPW) + warp * QPW;
    const int split = blockIdx.y;
    const int kbase = split * RANGE;
    const unsigned lt = (1u << lane) - 1u;

    float ax[QPW], ay[QPW], az[QPW], c0[QPW], thr[QPW];
    int cnt[QPW];
#pragma unroll
    for (int j = 0; j < QPW; j++) {
        int q = qbase + j;
        float qx = qpos[3 * q], qy = qpos[3 * q + 1], qz = qpos[3 * q + 2];
        c0[j] = fmaf(qx, qx, fmaf(qy, qy, qz * qz));
        ax[j] = -2.f * qx; ay[j] = -2.f * qy; az[j] = -2.f * qz;
        cnt[j] = 0;
    }

    // ---- load tile A (first 2048 of range) ----
    for (int i = tid; i < TILE; i += 32 * WPB) {
        int g = kbase + i;
        float x = kpos[3 * g], y = kpos[3 * g + 1], z = kpos[3 * g + 2];
        s_tile[i] = make_float4(x, y, z, fmaf(x, x, fmaf(y, y, z * z)));
    }
    __syncthreads();

    // ---- sample phase: per-lane sorted-4 minima -> safe threshold ----
    {
        float m[QPW][4];
#pragma unroll
        for (int j = 0; j < QPW; j++)
#pragma unroll
            for (int s = 0; s < 4; s++) m[j][s] = CUDART_INF_F;

        for (int i = lane; i < TILE; i += 32) {
            float4 kp = s_tile[i];
#pragma unroll
            for (int j = 0; j < QPW; j++) {
                float d = fmaf(ax[j], kp.x, c0[j] + kp.w);
                d = fmaf(ay[j], kp.y, d);
                d = fmaf(az[j], kp.z, d);
                d = fmaxf(d, 0.f);
                float t0 = fminf(m[j][0], d), t1 = fmaxf(m[j][0], d); m[j][0] = t0;
                float t2 = fminf(m[j][1], t1), t3 = fmaxf(m[j][1], t1); m[j][1] = t2;
                float t4 = fminf(m[j][2], t3), t5 = fmaxf(m[j][2], t3); m[j][2] = t4;
                m[j][3] = fminf(m[j][3], t5);
            }
        }
#pragma unroll
        for (int j = 0; j < QPW; j++) {
            unsigned lo = 0u, hi = 0x7f800000u;
#pragma unroll
            for (int it = 0; it < 16; it++) {
                unsigned mid = lo + ((hi - lo) >> 1);
                int c = 0;
#pragma unroll
                for (int s = 0; s < 4; s++) c += (__float_as_uint(m[j][s]) <= mid) ? 1 : 0;
                c = warp_sum_i(c);
                if (c >= KNN) hi = mid; else lo = mid + 1u;
            }
            thr[j] = __uint_as_float(hi);
        }
    }

    uint2* seg[QPW];
#pragma unroll
    for (int j = 0; j < QPW; j++)
        seg[j] = g_buf + ((size_t)(qbase + j) * NSPLIT + split) * CAPS;

    // ---- main scan: ballot append (coalesced packed writes) ----
    for (int t0 = 0; t0 < RANGE; t0 += TILE) {
        if (t0) {
            __syncthreads();
            for (int i = tid; i < TILE; i += 32 * WPB) {
                int g = kbase + t0 + i;
                float x = kpos[3 * g], y = kpos[3 * g + 1], z = kpos[3 * g + 2];
                s_tile[i] = make_float4(x, y, z, fmaf(x, x, fmaf(y, y, z * z)));
            }
            __syncthreads();
        }
        for (int i = lane; i < TILE; i += 32) {
            float4 kp = s_tile[i];
#pragma unroll
            for (int j = 0; j < QPW; j++) {
                float d = fmaf(ax[j], kp.x, c0[j] + kp.w);
                d = fmaf(ay[j], kp.y, d);
                d = fmaf(az[j], kp.z, d);
                bool p = (d <= thr[j]);
                unsigned m = __ballot_sync(FULLM, p);
                int pos = cnt[j] + __popc(m & lt);
                if (p && pos < CAPS)
                    seg[j][pos] = make_uint2(__float_as_uint(fmaxf(d, 0.f)),
                                             (unsigned)(kbase + t0 + i));
                cnt[j] += __popc(m);
            }
        }
    }
    if (lane == 0) {
#pragma unroll
        for (int j = 0; j < QPW; j++)
            g_cnt[(qbase + j) * NSPLIT + split] = min(cnt[j], CAPS);
    }
}

// ================= kernel 2: exact top-100 via 8-bit radix select ===========
// Warp per query, 8 warps/block, tiny smem -> high occupancy. Packed segments
// give fully coalesced uint2 reads straight from L2.
__global__ void __launch_bounds__(32 * FW) knn_final()
{
    __shared__ int s_hist[FW][257];
    __shared__ int s_tie[FW][64];
    __shared__ int s_ctr[FW][2];

    const int lane = threadIdx.x & 31, w = threadIdx.x >> 5;
    const int q = blockIdx.x * FW + w;

    const uint2* seg[NSPLIT];
    int c[NSPLIT];
#pragma unroll
    for (int s = 0; s < NSPLIT; s++) {
        seg[s] = g_buf + ((size_t)q * NSPLIT + s) * CAPS;
        c[s] = g_cnt[q * NSPLIT + s];
    }

    // ---- 4-round radix select: exact bits of the 100th smallest value ----
    unsigned prefix = 0;
    int kk = KNN;
#pragma unroll
    for (int shift = 24; shift >= 0; shift -= 8) {
        for (int b = lane; b < 256; b += 32) s_hist[w][b] = 0;
        __syncwarp();
        const unsigned himask = (shift == 24) ? 0u : ~((1u << (shift + 8)) - 1u);
#pragma unroll
        for (int s = 0; s < NSPLIT; s++) {
            for (int base = 0; base < c[s]; base += 32) {
                int i = base + lane;
                bool valid = (i < c[s]);
                unsigned bits = valid ? seg[s][i].x : 0u;
                valid = valid && ((bits & himask) == prefix);
                unsigned act = __ballot_sync(FULLM, valid);
                if (valid) {
                    int bin = (bits >> shift) & 0xFF;
                    unsigned peers = __match_any_sync(act, bin);
                    if ((int)__ffs(peers) - 1 == lane)
                        atomicAdd(&s_hist[w][bin], __popc(peers));
                }
            }
        }
        __syncwarp();
        // scan 256 bins (lane owns 8 consecutive)
        int loc[8], sum = 0;
#pragma unroll
        for (int t = 0; t < 8; t++) { loc[t] = sum; sum += s_hist[w][lane * 8 + t]; }
        int ex = sum;
#pragma unroll
        for (int o = 1; o < 32; o <<= 1) {
            int tv = __shfl_up_sync(FULLM, ex, o);
            if (lane >= o) ex += tv;
        }
        ex -= sum;
        int found = 999, cbf = 0;
#pragma unroll
        for (int t = 0; t < 8; t++) {
            int cb = ex + loc[t], ct = s_hist[w][lane * 8 + t];
            if (found == 999 && kk > cb && kk <= cb + ct) { found = lane * 8 + t; cbf = cb; }
        }
        int mf = warp_min_i(found);
        unsigned who = __ballot_sync(FULLM, found == mf);
        cbf = __shfl_sync(FULLM, cbf, __ffs(who) - 1);
        prefix |= ((unsigned)mf) << shift;
        kk -= cbf;
        __syncwarp();
    }
    const unsigned Tb = prefix;

    // ---- emit: all < Tb, then ties == Tb -> smallest kv indices ----
    if (lane == 0) { s_ctr[w][0] = 0; s_ctr[w][1] = 0; }
    __syncwarp();
    int* out = g_topk + (size_t)q * KNN;
#pragma unroll
    for (int s = 0; s < NSPLIT; s++) {
        for (int base = 0; base < c[s]; base += 32) {
            int i = base + lane;
            bool valid = (i < c[s]);
            uint2 e = valid ? seg[s][i] : make_uint2(0xffffffffu, 0u);
            if (valid && e.x < Tb) {
                out[atomicAdd(&s_ctr[w][0], 1)] = (int)e.y;
            } else if (valid && e.x == Tb) {
                int p = atomicAdd(&s_ctr[w][1], 1);
                if (p < 64) s_tie[w][p] = (int)e.y;
            }
        }
    }
    __syncwarp();
    const int nout = s_ctr[w][0];
    const int tc = min(s_ctr[w][1], 64);
    const int need = KNN - nout;
    for (int r = 0; r < need; r++) {
        int v0 = (lane < tc) ? s_tie[w][lane] : 0x7fffffff;
        int v1 = (lane + 32 < tc) ? s_tie[w][lane + 32] : 0x7fffffff;
        int mv = warp_min_i(min(v0, v1));
        if (v0 == mv && lane < tc) s_tie[w][lane] = 0x7fffffff;
        else if (v1 == mv && lane + 32 < tc) s_tie[w][lane + 32] = 0x7fffffff;
        if (lane == 0) out[nout + r] = mv;
        __syncwarp();
    }
}

// ================= kernel 3: gather attention + residual(2x) + LN ==========
__global__ void __launch_bounds__(CDIM) attn_ln(
    const float* __restrict__ qf, const float* __restrict__ kf,
    const float* __restrict__ vf, const float* __restrict__ gamma,
    const float* __restrict__ beta, float* __restrict__ out)
{
    const int q = blockIdx.x;
    const int tid = threadIdx.x, lane = tid & 31, warp = tid >> 5;

    __shared__ int    s_idx[KNN];
    __shared__ float  s_logit[KNN];
    __shared__ float  s_p[KNN];
    __shared__ float4 s_part[3][64];
    __shared__ float4 s_x4[64];
    __shared__ float  s_red[8];
    __shared__ float  s_mean, s_rstd, s_inv;

    if (tid < KNN) s_idx[tid] = g_topk[(size_t)q * KNN + tid];

    const float4* qf4 = (const float4*)(qf + (size_t)q * CDIM);
    const float4  qa = qf4[lane], qb = qf4[32 + lane];
    __syncthreads();

    // ---- QK^T: 4 neighbors per warp-round (8 LDG.128 in flight) ----
#pragma unroll
    for (int r = 0; r < 3; r++) {
        const int n = r * 32 + warp * 4;
        const float4* k0 = (const float4*)(kf + (size_t)s_idx[n + 0] * CDIM);
        const float4* k1 = (const float4*)(kf + (size_t)s_idx[n + 1] * CDIM);
        const float4* k2 = (const float4*)(kf + (size_t)s_idx[n + 2] * CDIM);
        const float4* k3 = (const float4*)(kf + (size_t)s_idx[n + 3] * CDIM);
        float4 a0 = k0[lane], b0 = k0[32 + lane];
        float4 a1 = k1[lane], b1 = k1[32 + lane];
        float4 a2 = k2[lane], b2 = k2[32 + lane];
        float4 a3 = k3[lane], b3 = k3[32 + lane];
        float s0 = qa.x * a0.x, s1 = qa.x * a1.x, s2 = qa.x * a2.x, s3 = qa.x * a3.x;
        s0 = fmaf(qa.y, a0.y, s0); s1 = fmaf(qa.y, a1.y, s1); s2 = fmaf(qa.y, a2.y, s2); s3 = fmaf(qa.y, a3.y, s3);
        s0 = fmaf(qa.z, a0.z, s0); s1 = fmaf(qa.z, a1.z, s1); s2 = fmaf(qa.z, a2.z, s2); s3 = fmaf(qa.z, a3.z, s3);
        s0 = fmaf(qa.w, a0.w, s0); s1 = fmaf(qa.w, a1.w, s1); s2 = fmaf(qa.w, a2.w, s2); s3 = fmaf(qa.w, a3.w, s3);
        s0 = fmaf(qb.x, b0.x, s0); s1 = fmaf(qb.x, b1.x, s1); s2 = fmaf(qb.x, b2.x, s2); s3 = fmaf(qb.x, b3.x, s3);
        s0 = fmaf(qb.y, b0.y, s0); s1 = fmaf(qb.y, b1.y, s1); s2 = fmaf(qb.y, b2.y, s2); s3 = fmaf(qb.y, b3.y, s3);
        s0 = fmaf(qb.z, b0.z, s0); s1 = fmaf(qb.z, b1.z, s1); s2 = fmaf(qb.z, b2.z, s2); s3 = fmaf(qb.z, b3.z, s3);
        s0 = fmaf(qb.w, b0.w, s0); s1 = fmaf(qb.w, b1.w, s1); s2 = fmaf(qb.w, b2.w, s2); s3 = fmaf(qb.w, b3.w, s3);
#pragma unroll
        for (int o = 16; o; o >>= 1) {
            s0 += __shfl_xor_sync(FULLM, s0, o);
            s1 += __shfl_xor_sync(FULLM, s1, o);
            s2 += __shfl_xor_sync(FULLM, s2, o);
            s3 += __shfl_xor_sync(FULLM, s3, o);
        }
        if (lane == 0) {
            s_logit[n + 0] = s0 * 0.0625f;
            s_logit[n + 1] = s1 * 0.0625f;
            s_logit[n + 2] = s2 * 0.0625f;
            s_logit[n + 3] = s3 * 0.0625f;
        }
    }
    if (warp < 4) {                  // tail: neighbors 96..99
        const int n = 96 + warp;
        const float4* kr = (const float4*)(kf + (size_t)s_idx[n] * CDIM);
        float4 ka = kr[lane], kb = kr[32 + lane];
        float s = qa.x * ka.x;
        s = fmaf(qa.y, ka.y, s); s = fmaf(qa.z, ka.z, s); s = fmaf(qa.w, ka.w, s);
        s = fmaf(qb.x, kb.x, s); s = fmaf(qb.y, kb.y, s);
        s = fmaf(qb.z, kb.z, s); s = fmaf(qb.w, kb.w, s);
        s = warp_sum_f(s);
        if (lane == 0) s_logit[n] = s * 0.0625f;
    }
    __syncthreads();

    // ---- softmax (warp 0) ----
    if (warp == 0) {
        float mx = -CUDART_INF_F;
        for (int i = lane; i < KNN; i += 32) mx = fmaxf(mx, s_logit[i]);
        mx = warp_max_f(mx);
        float sm = 0.f;
        for (int i = lane; i < KNN; i += 32) {
            float e = __expf(s_logit[i] - mx);
            s_p[i] = e; sm += e;
        }
        sm = warp_sum_f(sm);
        if (lane == 0) s_inv = 1.f / sm;
    }
    __syncthreads();

    // ---- PV: 4 neighbor-groups x 64 float4 cols, 4 accumulator chains ----
    const int g = warp >> 1;
    const int col = (warp & 1) * 32 + lane;
    float4 a0 = make_float4(0.f, 0.f, 0.f, 0.f), a1 = a0, a2 = a0, a3 = a0;
    int n = g;
    for (; n + 12 < KNN; n += 16) {
        const float4 v0 = ((const float4*)(vf + (size_t)s_idx[n]      * CDIM))[col];
        const float4 v1 = ((const float4*)(vf + (size_t)s_idx[n + 4]  * CDIM))[col];
        const float4 v2 = ((const float4*)(vf + (size_t)s_idx[n + 8]  * CDIM))[col];
        const float4 v3 = ((const float4*)(vf + (size_t)s_idx[n + 12] * CDIM))[col];
        const float p0 = s_p[n], p1 = s_p[n + 4], p2 = s_p[n + 8], p3 = s_p[n + 12];
        a0.x = fmaf(p0, v0.x, a0.x); a1.x = fmaf(p1, v1.x, a1.x); a2.x = fmaf(p2, v2.x, a2.x); a3.x = fmaf(p3, v3.x, a3.x);
        a0.y = fmaf(p0, v0.y, a0.y); a1.y = fmaf(p1, v1.y, a1.y); a2.y = fmaf(p2, v2.y, a2.y); a3.y = fmaf(p3, v3.y, a3.y);
        a0.z = fmaf(p0, v0.z, a0.z); a1.z = fmaf(p1, v1.z, a1.z); a2.z = fmaf(p2, v2.z, a2.z); a3.z = fmaf(p3, v3.z, a3.z);
        a0.w = fmaf(p0, v0.w, a0.w); a1.w = fmaf(p1, v1.w, a1.w); a2.w = fmaf(p2, v2.w, a2.w); a3.w = fmaf(p3, v3.w, a3.w);
    }
    for (; n < KNN; n += 4) {
        const float4 v0 = ((const float4*)(vf + (size_t)s_idx[n] * CDIM))[col];
        const float p0 = s_p[n];
        a0.x = fmaf(p0, v0.x, a0.x);
        a0.y = fmaf(p0, v0.y, a0.y);
        a0.z = fmaf(p0, v0.z, a0.z);
        a0.w = fmaf(p0, v0.w, a0.w);
    }
    float4 acc = make_float4((a0.x + a1.x) + (a2.x + a3.x),
                             (a0.y + a1.y) + (a2.y + a3.y),
                             (a0.z + a1.z) + (a2.z + a3.z),
                             (a0.w + a1.w) + (a2.w + a3.w));
    if (g) s_part[g - 1][col] = acc;
    __syncthreads();
    if (g == 0) {
        float4 a = s_part[0][col], b = s_part[1][col], c = s_part[2][col];
        float sc = 2.f * s_inv;                        // res fully overwritten: y = 2x
        s_x4[col] = make_float4((acc.x + a.x + b.x + c.x) * sc,
                                (acc.y + a.y + b.y + c.y) * sc,
                                (acc.z + a.z + b.z + c.z) * sc,
                                (acc.w + a.w + b.w + c.w) * sc);
    }
    __syncthreads();

    // ---- LayerNorm over CDIM ----
    float y = ((const float*)s_x4)[tid];
    float s = warp_sum_f(y);
    if (lane == 0) s_red[warp] = s;
    __syncthreads();
    if (warp == 0) {
        float v = (lane < 8) ? s_red[lane] : 0.f;
        v = warp_sum_f(v);
        if (lane == 0) s_mean = v * (1.f / CDIM);
    }
    __syncthreads();
    float d = y - s_mean;
    float s2 = warp_sum_f(d * d);
    if (lane == 0) s_red[warp] = s2;
    __syncthreads();
    if (warp == 0) {
        float v = (lane < 8) ? s_red[lane] : 0.f;
        v = warp_sum_f(v);
        if (lane == 0) s_rstd = rsqrtf(v * (1.f / CDIM) + 1e-5f);
    }
    __syncthreads();

    out[(size_t)q * CDIM + tid] = d * s_rstd * gamma[tid] + beta[tid];
}

// ---------------- launch ----------------
extern "C" void kernel_launch(void* const* d_in, const int* in_sizes, int n_in,
                              void* d_out, int out_size) {
    (void)in_sizes; (void)n_in; (void)out_size;
    const float* qf    = (const float*)d_in[1];
    const float* kf    = (const float*)d_in[2];
    const float* vf    = (const float*)d_in[3];
    const float* qpos  = (const float*)d_in[4];
    const float* kpos  = (const float*)d_in[5];
    const float* gamma = (const float*)d_in[6];
    const float* beta  = (const float*)d_in[7];

    knn_scan<<<dim3(NQ / (WPB * QPW), NSPLIT), 32 * WPB>>>(qpos, kpos);
    knn_final<<<NQ / FW, 32 * FW>>>();
    attn_ln<<<NQ, CDIM>>>(qf, kf, vf, gamma, beta, (float*)d_out);
}

// round 7
// speedup vs baseline: 1.7232x; 1.1968x over previous
#include <cuda_runtime.h>
#include <math_constants.h>

#define NQ     4096
#define NKV    32768
#define CDIM   256
#define KNN    100
#define NSPLIT 4
#define RANGE  (NKV / NSPLIT)     // 8192
#define TILE   1024               // scan tile (16KB smem)
#define STILE  2048               // thr-kernel sample tile
#define CAPS   1024               // per (query,split) segment capacity
#define QPW    4
#define WPB    4
#define FW     8                  // warps per block in knn_final
#define AW     4                  // warps (queries) per block in attn
#define FULLM  0xffffffffu

// ---------------- static scratch ----------------
__device__ uint2 g_buf[(size_t)NQ * NSPLIT * CAPS];  // {d2 bits (>=0), kv idx}
__device__ int   g_cnt[NQ * NSPLIT];
__device__ float g_thr[NQ];
__device__ int   g_topk[(size_t)NQ * KNN];

// ---------------- helpers ----------------
__device__ __forceinline__ int warp_sum_i(int v) {
#pragma unroll
    for (int o = 16; o; o >>= 1) v += __shfl_xor_sync(FULLM, v, o);
    return v;
}
__device__ __forceinline__ float warp_sum_f(float v) {
#pragma unroll
    for (int o = 16; o; o >>= 1) v += __shfl_xor_sync(FULLM, v, o);
    return v;
}
__device__ __forceinline__ float warp_max_f(float v) {
#pragma unroll
    for (int o = 16; o; o >>= 1) v = fmaxf(v, __shfl_xor_sync(FULLM, v, o));
    return v;
}
__device__ __forceinline__ int warp_min_i(int v) {
#pragma unroll
    for (int o = 16; o; o >>= 1) v = min(v, __shfl_xor_sync(FULLM, v, o));
    return v;
}

// ================= kernel 0: per-query safe threshold =================
// Warp per query (8/block). Sample = first 4096 kv points (2 smem tiles).
// Per-lane sorted-4 minima over 128 candidates -> kth(k=100) of the 128
// stash values (binary search on bits; values clamped >= 0). Stash and
// sample are subsets of the population, so thr >= true global 100th: SAFE.
__global__ void __launch_bounds__(256) knn_thr(
    const float* __restrict__ qpos, const float* __restrict__ kpos)
{
    __shared__ float4 s_tile[STILE];
    const int tid = threadIdx.x, lane = tid & 31, w = tid >> 5;
    const int q = blockIdx.x * 8 + w;

    const float qx = qpos[3 * q], qy = qpos[3 * q + 1], qz = qpos[3 * q + 2];
    const float c0 = fmaf(qx, qx, fmaf(qy, qy, qz * qz));
    const float ax = -2.f * qx, ay = -2.f * qy, az = -2.f * qz;

    float m0 = CUDART_INF_F, m1 = CUDART_INF_F, m2 = CUDART_INF_F, m3 = CUDART_INF_F;

#pragma unroll
    for (int pass = 0; pass < 2; pass++) {
        __syncthreads();
        for (int i = tid; i < STILE; i += 256) {
            int g = pass * STILE + i;
            float x = kpos[3 * g], y = kpos[3 * g + 1], z = kpos[3 * g + 2];
            s_tile[i] = make_float4(x, y, z, fmaf(x, x, fmaf(y, y, z * z)));
        }
        __syncthreads();
        for (int i = lane; i < STILE; i += 32) {
            float4 kp = s_tile[i];
            float d = fmaf(ax, kp.x, c0 + kp.w);
            d = fmaf(ay, kp.y, d);
            d = fmaf(az, kp.z, d);
            d = fmaxf(d, 0.f);
            float t0 = fminf(m0, d), t1 = fmaxf(m0, d); m0 = t0;
            float t2 = fminf(m1, t1), t3 = fmaxf(m1, t1); m1 = t2;
            float t4 = fminf(m2, t3), t5 = fmaxf(m2, t3); m2 = t4;
            m3 = fminf(m3, t5);
        }
    }

    unsigned lo = 0u, hi = 0x7f800000u;
#pragma unroll
    for (int it = 0; it < 24; it++) {
        unsigned mid = lo + ((hi - lo) >> 1);
        int c = (__float_as_uint(m0) <= mid) + (__float_as_uint(m1) <= mid)
              + (__float_as_uint(m2) <= mid) + (__float_as_uint(m3) <= mid);
        c = warp_sum_i(c);
        if (c >= KNN) hi = mid; else lo = mid + 1u;
    }
    if (lane == 0) g_thr[q] = __uint_as_float(hi);
}

// ================= kernel 1: candidate scan (KV-split, no sampling) ========
// grid = (NQ/16, NSPLIT). Warp: 4 queries over one 8192-wide KV range.
// Hot loop: 3 FMA + compare (c0 folded into threshold), ballot append to
// packed per-(q,split) segment (coalesced writes).
__global__ void __launch_bounds__(32 * WPB) knn_scan(
    const float* __restrict__ qpos, const float* __restrict__ kpos)
{
    __shared__ float4 s_tile[TILE];

    const int tid = threadIdx.x, lane = tid & 31, warp = tid >> 5;
    const int qbase = blockIdx.x * (WPB * QPW) + warp * QPW;
    const int split = blockIdx.y;
    const int kbase = split * RANGE;
    const unsigned lt = (1u << lane) - 1u;

    float ax[QPW], ay[QPW], az[QPW], c0[QPW], tj[QPW];
    int cnt[QPW];
#pragma unroll
    for (int j = 0; j < QPW; j++) {
        int q = qbase + j;
        float qx = qpos[3 * q], qy = qpos[3 * q + 1], qz = qpos[3 * q + 2];
        c0[j] = fmaf(qx, qx, fmaf(qy, qy, qz * qz));
        ax[j] = -2.f * qx; ay[j] = -2.f * qy; az[j] = -2.f * qz;
        // bump covers FMA-order rounding diffs between thr/scan kernels;
        // margin vs the ~900th-rank threshold value is enormous.
        tj[j] = g_thr[q] * 1.000002f - c0[j];
        cnt[j] = 0;
    }

    uint2* seg[QPW];
#pragma unroll
    for (int j = 0; j < QPW; j++)
        seg[j] = g_buf + ((size_t)(qbase + j) * NSPLIT + split) * CAPS;

    for (int t0 = 0; t0 < RANGE; t0 += TILE) {
        __syncthreads();
        for (int i = tid; i < TILE; i += 32 * WPB) {
            int g = kbase + t0 + i;
            float x = kpos[3 * g], y = kpos[3 * g + 1], z = kpos[3 * g + 2];
            s_tile[i] = make_float4(x, y, z, fmaf(x, x, fmaf(y, y, z * z)));
        }
        __syncthreads();
        for (int i = lane; i < TILE; i += 32) {
            float4 kp = s_tile[i];
#pragma unroll
            for (int j = 0; j < QPW; j++) {
                float dd = fmaf(ax[j], kp.x, kp.w);
                dd = fmaf(ay[j], kp.y, dd);
                dd = fmaf(az[j], kp.z, dd);
                bool p = (dd <= tj[j]);
                unsigned m = __ballot_sync(FULLM, p);
                int pos = cnt[j] + __popc(m & lt);
                if (p && pos < CAPS)
                    seg[j][pos] = make_uint2(__float_as_uint(fmaxf(dd + c0[j], 0.f)),
                                             (unsigned)(kbase + t0 + i));
                cnt[j] += __popc(m);
            }
        }
    }
    if (lane == 0) {
#pragma unroll
        for (int j = 0; j < QPW; j++)
            g_cnt[(qbase + j) * NSPLIT + split] = min(cnt[j], CAPS);
    }
}

// ================= kernel 2: exact top-100 via 8-bit radix select ===========
__global__ void __launch_bounds__(32 * FW) knn_final()
{
    __shared__ int s_hist[FW][257];
    __shared__ int s_tie[FW][64];
    __shared__ int s_ctr[FW][2];

    const int lane = threadIdx.x & 31, w = threadIdx.x >> 5;
    const int q = blockIdx.x * FW + w;

    const uint2* seg[NSPLIT];
    int c[NSPLIT];
#pragma unroll
    for (int s = 0; s < NSPLIT; s++) {
        seg[s] = g_buf + ((size_t)q * NSPLIT + s) * CAPS;
        c[s] = g_cnt[q * NSPLIT + s];
    }

    unsigned prefix = 0;
    int kk = KNN;
#pragma unroll
    for (int shift = 24; shift >= 0; shift -= 8) {
        for (int b = lane; b < 256; b += 32) s_hist[w][b] = 0;
        __syncwarp();
        const unsigned himask = (shift == 24) ? 0u : ~((1u << (shift + 8)) - 1u);
#pragma unroll
        for (int s = 0; s < NSPLIT; s++) {
            for (int base = 0; base < c[s]; base += 32) {
                int i = base + lane;
                bool valid = (i < c[s]);
                unsigned bits = valid ? seg[s][i].x : 0u;
                valid = valid && ((bits & himask) == prefix);
                unsigned act = __ballot_sync(FULLM, valid);
                if (valid) {
                    int bin = (bits >> shift) & 0xFF;
                    unsigned peers = __match_any_sync(act, bin);
                    if ((int)__ffs(peers) - 1 == lane)
                        atomicAdd(&s_hist[w][bin], __popc(peers));
                }
            }
        }
        __syncwarp();
        int loc[8], sum = 0;
#pragma unroll
        for (int t = 0; t < 8; t++) { loc[t] = sum; sum += s_hist[w][lane * 8 + t]; }
        int ex = sum;
#pragma unroll
        for (int o = 1; o < 32; o <<= 1) {
            int tv = __shfl_up_sync(FULLM, ex, o);
            if (lane >= o) ex += tv;
        }
        ex -= sum;
        int found = 999, cbf = 0;
#pragma unroll
        for (int t = 0; t < 8; t++) {
            int cb = ex + loc[t], ct = s_hist[w][lane * 8 + t];
            if (found == 999 && kk > cb && kk <= cb + ct) { found = lane * 8 + t; cbf = cb; }
        }
        int mf = warp_min_i(found);
        unsigned who = __ballot_sync(FULLM, found == mf);
        cbf = __shfl_sync(FULLM, cbf, __ffs(who) - 1);
        prefix |= ((unsigned)mf) << shift;
        kk -= cbf;
        __syncwarp();
    }
    const unsigned Tb = prefix;

    if (lane == 0) { s_ctr[w][0] = 0; s_ctr[w][1] = 0; }
    __syncwarp();
    int* out = g_topk + (size_t)q * KNN;
#pragma unroll
    for (int s = 0; s < NSPLIT; s++) {
        for (int base = 0; base < c[s]; base += 32) {
            int i = base + lane;
            bool valid = (i < c[s]);
            uint2 e = valid ? seg[s][i] : make_uint2(0xffffffffu, 0u);
            if (valid && e.x < Tb) {
                out[atomicAdd(&s_ctr[w][0], 1)] = (int)e.y;
            } else if (valid && e.x == Tb) {
                int p = atomicAdd(&s_ctr[w][1], 1);
                if (p < 64) s_tie[w][p] = (int)e.y;
            }
        }
    }
    __syncwarp();
    const int nout = s_ctr[w][0];
    const int tc = min(s_ctr[w][1], 64);
    const int need = KNN - nout;
    for (int r = 0; r < need; r++) {
        int v0 = (lane < tc) ? s_tie[w][lane] : 0x7fffffff;
        int v1 = (lane + 32 < tc) ? s_tie[w][lane + 32] : 0x7fffffff;
        int mv = warp_min_i(min(v0, v1));
        if (v0 == mv && lane < tc) s_tie[w][lane] = 0x7fffffff;
        else if (v1 == mv && lane + 32 < tc) s_tie[w][lane + 32] = 0x7fffffff;
        if (lane == 0) out[nout + r] = mv;
        __syncwarp();
    }
}

// ================= kernel 3: attention + residual(2x) + LN, warp/query =====
// One warp per query: no block barriers. Logits/probabilities staged in a
// per-warp smem row; QK 4 rows in flight (8 LDG.128), PV 2 chains x 4 rows.
__global__ void __launch_bounds__(32 * AW) attn_ln(
    const float* __restrict__ qf, const float* __restrict__ kf,
    const float* __restrict__ vf, const float* __restrict__ gamma,
    const float* __restrict__ beta, float* __restrict__ out)
{
    __shared__ int   s_idx[AW][100];   // 400B rows (16B aligned)
    __shared__ float s_p[AW][104];     // 416B rows (16B aligned)

    const int lane = threadIdx.x & 31, w = threadIdx.x >> 5;
    const int q = blockIdx.x * AW + w;

    for (int i = lane; i < KNN; i += 32) s_idx[w][i] = g_topk[(size_t)q * KNN + i];

    const float4* qf4 = (const float4*)(qf + (size_t)q * CDIM);
    const float4 qa = qf4[lane], qb = qf4[32 + lane];
    __syncwarp();

    // ---- QK^T: 25 groups of 4 rows ----
    for (int gr = 0; gr < 25; gr++) {
        const int4 id = *(const int4*)&s_idx[w][gr * 4];
        const float4* k0 = (const float4*)(kf + (size_t)id.x * CDIM);
        const float4* k1 = (const float4*)(kf + (size_t)id.y * CDIM);
        const float4* k2 = (const float4*)(kf + (size_t)id.z * CDIM);
        const float4* k3 = (const float4*)(kf + (size_t)id.w * CDIM);
        float4 a0 = k0[lane], b0 = k0[32 + lane];
        float4 a1 = k1[lane], b1 = k1[32 + lane];
        float4 a2 = k2[lane], b2 = k2[32 + lane];
        float4 a3 = k3[lane], b3 = k3[32 + lane];
        float s0 = qa.x * a0.x, s1 = qa.x * a1.x, s2 = qa.x * a2.x, s3 = qa.x * a3.x;
        s0 = fmaf(qa.y, a0.y, s0); s1 = fmaf(qa.y, a1.y, s1); s2 = fmaf(qa.y, a2.y, s2); s3 = fmaf(qa.y, a3.y, s3);
        s0 = fmaf(qa.z, a0.z, s0); s1 = fmaf(qa.z, a1.z, s1); s2 = fmaf(qa.z, a2.z, s2); s3 = fmaf(qa.z, a3.z, s3);
        s0 = fmaf(qa.w, a0.w, s0); s1 = fmaf(qa.w, a1.w, s1); s2 = fmaf(qa.w, a2.w, s2); s3 = fmaf(qa.w, a3.w, s3);
        s0 = fmaf(qb.x, b0.x, s0); s1 = fmaf(qb.x, b1.x, s1); s2 = fmaf(qb.x, b2.x, s2); s3 = fmaf(qb.x, b3.x, s3);
        s0 = fmaf(qb.y, b0.y, s0); s1 = fmaf(qb.y, b1.y, s1); s2 = fmaf(qb.y, b2.y, s2); s3 = fmaf(qb.y, b3.y, s3);
        s0 = fmaf(qb.z, b0.z, s0); s1 = fmaf(qb.z, b1.z, s1); s2 = fmaf(qb.z, b2.z, s2); s3 = fmaf(qb.z, b3.z, s3);
        s0 = fmaf(qb.w, b0.w, s0); s1 = fmaf(qb.w, b1.w, s1); s2 = fmaf(qb.w, b2.w, s2); s3 = fmaf(qb.w, b3.w, s3);
#pragma unroll
        for (int o = 16; o; o >>= 1) {
            s0 += __shfl_xor_sync(FULLM, s0, o);
            s1 += __shfl_xor_sync(FULLM, s1, o);
            s2 += __shfl_xor_sync(FULLM, s2, o);
            s3 += __shfl_xor_sync(FULLM, s3, o);
        }
        if (lane == 0)
            *(float4*)&s_p[w][gr * 4] =
                make_float4(s0 * 0.0625f, s1 * 0.0625f, s2 * 0.0625f, s3 * 0.0625f);
    }
    __syncwarp();

    // ---- softmax within the warp ----
    float l0 = s_p[w][lane], l1 = s_p[w][lane + 32], l2 = s_p[w][lane + 64];
    float l3 = (lane < 4) ? s_p[w][lane + 96] : -CUDART_INF_F;
    float mx = warp_max_f(fmaxf(fmaxf(l0, l1), fmaxf(l2, l3)));
    float e0 = __expf(l0 - mx), e1 = __expf(l1 - mx), e2 = __expf(l2 - mx);
    float e3 = (lane < 4) ? __expf(l3 - mx) : 0.f;
    float sm = warp_sum_f((e0 + e1) + (e2 + e3));
    s_p[w][lane] = e0; s_p[w][lane + 32] = e1; s_p[w][lane + 64] = e2;
    if (lane < 4) s_p[w][lane + 96] = e3;
    const float sc = 2.f / sm;   // res fully overwritten by x: y = 2x; fold 1/sum
    __syncwarp();

    // ---- PV: 2 chains x 4 rows per group ----
    float4 A0 = make_float4(0.f, 0.f, 0.f, 0.f), B0 = A0, A1 = A0, B1 = A0;
    for (int gr = 0; gr < 25; gr++) {
        const int4 id = *(const int4*)&s_idx[w][gr * 4];
        const float4 p4 = *(const float4*)&s_p[w][gr * 4];
        const float4* v0 = (const float4*)(vf + (size_t)id.x * CDIM);
        const float4* v1 = (const float4*)(vf + (size_t)id.y * CDIM);
        const float4* v2 = (const float4*)(vf + (size_t)id.z * CDIM);
        const float4* v3 = (const float4*)(vf + (size_t)id.w * CDIM);
        float4 va0 = v0[lane], vb0 = v0[32 + lane];
        float4 va1 = v1[lane], vb1 = v1[32 + lane];
        float4 va2 = v2[lane], vb2 = v2[32 + lane];
        float4 va3 = v3[lane], vb3 = v3[32 + lane];
        A0.x = fmaf(p4.x, va0.x, A0.x); A0.y = fmaf(p4.x, va0.y, A0.y);
        A0.z = fmaf(p4.x, va0.z, A0.z); A0.w = fmaf(p4.x, va0.w, A0.w);
        B0.x = fmaf(p4.x, vb0.x, B0.x); B0.y = fmaf(p4.x, vb0.y, B0.y);
        B0.z = fmaf(p4.x, vb0.z, B0.z); B0.w = fmaf(p4.x, vb0.w, B0.w);
        A1.x = fmaf(p4.y, va1.x, A1.x); A1.y = fmaf(p4.y, va1.y, A1.y);
        A1.z = fmaf(p4.y, va1.z, A1.z); A1.w = fmaf(p4.y, va1.w, A1.w);
        B1.x = fmaf(p4.y, vb1.x, B1.x); B1.y = fmaf(p4.y, vb1.y, B1.y);
        B1.z = fmaf(p4.y, vb1.z, B1.z); B1.w = fmaf(p4.y, vb1.w, B1.w);
        A0.x = fmaf(p4.z, va2.x, A0.x); A0.y = fmaf(p4.z, va2.y, A0.y);
        A0.z = fmaf(p4.z, va2.z, A0.z); A0.w = fmaf(p4.z, va2.w, A0.w);
        B0.x = fmaf(p4.z, vb2.x, B0.x); B0.y = fmaf(p4.z, vb2.y, B0.y);
        B0.z = fmaf(p4.z, vb2.z, B0.z); B0.w = fmaf(p4.z, vb2.w, B0.w);
        A1.x = fmaf(p4.w, va3.x, A1.x); A1.y = fmaf(p4.w, va3.y, A1.y);
        A1.z = fmaf(p4.w, va3.z, A1.z); A1.w = fmaf(p4.w, va3.w, A1.w);
        B1.x = fmaf(p4.w, vb3.x, B1.x); B1.y = fmaf(p4.w, vb3.y, B1.y);
        B1.z = fmaf(p4.w, vb3.z, B1.z); B1.w = fmaf(p4.w, vb3.w, B1.w);
    }
    float4 A = make_float4((A0.x + A1.x) * sc, (A0.y + A1.y) * sc,
                           (A0.z + A1.z) * sc, (A0.w + A1.w) * sc);
    float4 B = make_float4((B0.x + B1.x) * sc, (B0.y + B1.y) * sc,
                           (B0.z + B1.z) * sc, (B0.w + B1.w) * sc);

    // ---- LayerNorm within the warp ----
    float s = ((A.x + A.y) + (A.z + A.w)) + ((B.x + B.y) + (B.z + B.w));
    const float mean = warp_sum_f(s) * (1.f / CDIM);
    float dAx = A.x - mean, dAy = A.y - mean, dAz = A.z - mean, dAw = A.w - mean;
    float dBx = B.x - mean, dBy = B.y - mean, dBz = B.z - mean, dBw = B.w - mean;
    float s2 = ((dAx * dAx + dAy * dAy) + (dAz * dAz + dAw * dAw))
             + ((dBx * dBx + dBy * dBy) + (dBz * dBz + dBw * dBw));
    const float rstd = rsqrtf(warp_sum_f(s2) * (1.f / CDIM) + 1e-5f);

    const float4* g4 = (const float4*)gamma;
    const float4* b4 = (const float4*)beta;
    float4 ga = g4[lane], gb = g4[32 + lane];
    float4 ba = b4[lane], bb = b4[32 + lane];
    float4* o4 = (float4*)(out + (size_t)q * CDIM);
    o4[lane] = make_float4(fmaf(dAx * rstd, ga.x, ba.x),
                           fmaf(dAy * rstd, ga.y, ba.y),
                           fmaf(dAz * rstd, ga.z, ba.z),
                           fmaf(dAw * rstd, ga.w, ba.w));
    o4[32 + lane] = make_float4(fmaf(dBx * rstd, gb.x, bb.x),
                                fmaf(dBy * rstd, gb.y, bb.y),
                                fmaf(dBz * rstd, gb.z, bb.z),
                                fmaf(dBw * rstd, gb.w, bb.w));
}

// ---------------- launch ----------------
extern "C" void kernel_launch(void* const* d_in, const int* in_sizes, int n_in,
                              void* d_out, int out_size) {
    (void)in_sizes; (void)n_in; (void)out_size;
    const float* qf    = (const float*)d_in[1];
    const float* kf    = (const float*)d_in[2];
    const float* vf    = (const float*)d_in[3];
    const float* qpos  = (const float*)d_in[4];
    const float* kpos  = (const float*)d_in[5];
    const float* gamma = (const float*)d_in[6];
    const float* beta  = (const float*)d_in[7];

    knn_thr<<<NQ / 8, 256>>>(qpos, kpos);
    knn_scan<<<dim3(NQ / (WPB * QPW), NSPLIT), 32 * WPB>>>(qpos, kpos);
    knn_final<<<NQ / FW, 32 * FW>>>();
    attn_ln<<<NQ / AW, 32 * AW>>>(qf, kf, vf, gamma, beta, (float*)d_out);
}

// round 8
// speedup vs baseline: 1.9753x; 1.1463x over previous
#include <cuda_runtime.h>
#include <math_constants.h>

#define NQ     4096
#define NKV    32768
#define CDIM   256
#define KNN    100
#define NSPLIT 8
#define RANGE  (NKV / NSPLIT)     // 4096
#define TILE   1024               // scan tile (16KB smem)
#define STILE  2048               // thr-kernel sample tile
#define CAPS   768                // per (query,split) segment capacity
#define QPW    4
#define WPB    4
#define AW     4                  // warps (queries) per block in attn
#define FULLM  0xffffffffu

// ---------------- static scratch ----------------
__device__ uint2 g_buf[(size_t)NQ * NSPLIT * CAPS];  // {d2 bits (>=0), kv idx}
__device__ int   g_cnt[NQ * NSPLIT];
__device__ float g_thr[NQ];

// ---------------- helpers ----------------
__device__ __forceinline__ int warp_sum_i(int v) {
#pragma unroll
    for (int o = 16; o; o >>= 1) v += __shfl_xor_sync(FULLM, v, o);
    return v;
}
__device__ __forceinline__ float warp_sum_f(float v) {
#pragma unroll
    for (int o = 16; o; o >>= 1) v += __shfl_xor_sync(FULLM, v, o);
    return v;
}
__device__ __forceinline__ float warp_max_f(float v) {
#pragma unroll
    for (int o = 16; o; o >>= 1) v = fmaxf(v, __shfl_xor_sync(FULLM, v, o));
    return v;
}
__device__ __forceinline__ int warp_min_i(int v) {
#pragma unroll
    for (int o = 16; o; o >>= 1) v = min(v, __shfl_xor_sync(FULLM, v, o));
    return v;
}

// ================= kernel 0: per-query safe threshold =================
// Warp per query (8/block). Sample = first 4096 kv points. Per-lane sorted-4
// minima -> kth(k=100) of the 128 stash values; stash/sample are population
// subsets so thr >= true global 100th: SAFE admit filter.
__global__ void __launch_bounds__(256) knn_thr(
    const float* __restrict__ qpos, const float* __restrict__ kpos)
{
    __shared__ float4 s_tile[STILE];
    const int tid = threadIdx.x, lane = tid & 31, w = tid >> 5;
    const int q = blockIdx.x * 8 + w;

    const float qx = qpos[3 * q], qy = qpos[3 * q + 1], qz = qpos[3 * q + 2];
    const float c0 = fmaf(qx, qx, fmaf(qy, qy, qz * qz));
    const float ax = -2.f * qx, ay = -2.f * qy, az = -2.f * qz;

    float m0 = CUDART_INF_F, m1 = CUDART_INF_F, m2 = CUDART_INF_F, m3 = CUDART_INF_F;

#pragma unroll
    for (int pass = 0; pass < 2; pass++) {
        __syncthreads();
        for (int i = tid; i < STILE; i += 256) {
            int g = pass * STILE + i;
            float x = kpos[3 * g], y = kpos[3 * g + 1], z = kpos[3 * g + 2];
            s_tile[i] = make_float4(x, y, z, fmaf(x, x, fmaf(y, y, z * z)));
        }
        __syncthreads();
        for (int i = lane; i < STILE; i += 32) {
            float4 kp = s_tile[i];
            float d = fmaf(ax, kp.x, c0 + kp.w);
            d = fmaf(ay, kp.y, d);
            d = fmaf(az, kp.z, d);
            d = fmaxf(d, 0.f);
            float t0 = fminf(m0, d), t1 = fmaxf(m0, d); m0 = t0;
            float t2 = fminf(m1, t1), t3 = fmaxf(m1, t1); m1 = t2;
            float t4 = fminf(m2, t3), t5 = fmaxf(m2, t3); m2 = t4;
            m3 = fminf(m3, t5);
        }
    }

    unsigned lo = 0u, hi = 0x7f800000u;
#pragma unroll
    for (int it = 0; it < 24; it++) {
        unsigned mid = lo + ((hi - lo) >> 1);
        int c = (__float_as_uint(m0) <= mid) + (__float_as_uint(m1) <= mid)
              + (__float_as_uint(m2) <= mid) + (__float_as_uint(m3) <= mid);
        c = warp_sum_i(c);
        if (c >= KNN) hi = mid; else lo = mid + 1u;
    }
    if (lane == 0) g_thr[q] = __uint_as_float(hi);
}

// ================= kernel 1: candidate scan (KV-split x8) =================
// grid = (NQ/16, NSPLIT). Warp: 4 queries over one 4096-wide KV range.
// Hot loop: 3 FMA + compare (c0 folded into threshold), ballot append to
// packed per-(q,split) segment (coalesced writes).
__global__ void __launch_bounds__(32 * WPB, 8) knn_scan(
    const float* __restrict__ qpos, const float* __restrict__ kpos)
{
    __shared__ float4 s_tile[TILE];

    const int tid = threadIdx.x, lane = tid & 31, warp = tid >> 5;
    const int qbase = blockIdx.x * (WPB * QPW) + warp * QPW;
    const int split = blockIdx.y;
    const int kbase = split * RANGE;
    const unsigned lt = (1u << lane) - 1u;

    float ax[QPW], ay[QPW], az[QPW], c0[QPW], tj[QPW];
    int cnt[QPW];
#pragma unroll
    for (int j = 0; j < QPW; j++) {
        int q = qbase + j;
        float qx = qpos[3 * q], qy = qpos[3 * q + 1], qz = qpos[3 * q + 2];
        c0[j] = fmaf(qx, qx, fmaf(qy, qy, qz * qz));
        ax[j] = -2.f * qx; ay[j] = -2.f * qy; az[j] = -2.f * qz;
        // bump covers FMA-order rounding diffs between thr/scan kernels
        tj[j] = g_thr[q] * 1.000002f - c0[j];
        cnt[j] = 0;
    }

    uint2* seg[QPW];
#pragma unroll
    for (int j = 0; j < QPW; j++)
        seg[j] = g_buf + ((size_t)(qbase + j) * NSPLIT + split) * CAPS;

    for (int t0 = 0; t0 < RANGE; t0 += TILE) {
        __syncthreads();
        for (int i = tid; i < TILE; i += 32 * WPB) {
            int g = kbase + t0 + i;
            float x = kpos[3 * g], y = kpos[3 * g + 1], z = kpos[3 * g + 2];
            s_tile[i] = make_float4(x, y, z, fmaf(x, x, fmaf(y, y, z * z)));
        }
        __syncthreads();
        for (int i = lane; i < TILE; i += 32) {
            float4 kp = s_tile[i];
#pragma unroll
            for (int j = 0; j < QPW; j++) {
                float dd = fmaf(ax[j], kp.x, kp.w);
                dd = fmaf(ay[j], kp.y, dd);
                dd = fmaf(az[j], kp.z, dd);
                bool p = (dd <= tj[j]);
                unsigned m = __ballot_sync(FULLM, p);
                int pos = cnt[j] + __popc(m & lt);
                if (p && pos < CAPS)
                    seg[j][pos] = make_uint2(__float_as_uint(fmaxf(dd + c0[j], 0.f)),
                                             (unsigned)(kbase + t0 + i));
                cnt[j] += __popc(m);
            }
        }
    }
    if (lane == 0) {
#pragma unroll
        for (int j = 0; j < QPW; j++)
            g_cnt[(qbase + j) * NSPLIT + split] = min(cnt[j], CAPS);
    }
}

// ================= kernel 2: fused select + attention + LN, warp/query =====
__global__ void __launch_bounds__(32 * AW) attn_ln(
    const float* __restrict__ qf, const float* __restrict__ kf,
    const float* __restrict__ vf, const float* __restrict__ gamma,
    const float* __restrict__ beta, float* __restrict__ out)
{
    __shared__ int   s_idx[AW][100];
    __shared__ float s_p[AW][104];
    __shared__ int   s_hist[AW][257];
    __shared__ int   s_tie[AW][64];
    __shared__ int   s_ctr[AW][2];

    const int lane = threadIdx.x & 31, w = threadIdx.x >> 5;
    const int q = blockIdx.x * AW + w;

    // ---------- exact top-100 via 8-bit radix select (per warp) ----------
    {
        const uint2* seg[NSPLIT];
        int c[NSPLIT];
#pragma unroll
        for (int s = 0; s < NSPLIT; s++) {
            seg[s] = g_buf + ((size_t)q * NSPLIT + s) * CAPS;
            c[s] = g_cnt[q * NSPLIT + s];
        }

        unsigned prefix = 0;
        int kk = KNN;
#pragma unroll
        for (int shift = 24; shift >= 0; shift -= 8) {
            for (int b = lane; b < 256; b += 32) s_hist[w][b] = 0;
            __syncwarp();
            const unsigned himask = (shift == 24) ? 0u : ~((1u << (shift + 8)) - 1u);
#pragma unroll
            for (int s = 0; s < NSPLIT; s++) {
                for (int base = 0; base < c[s]; base += 32) {
                    int i = base + lane;
                    bool valid = (i < c[s]);
                    unsigned bits = valid ? seg[s][i].x : 0u;
                    valid = valid && ((bits & himask) == prefix);
                    unsigned act = __ballot_sync(FULLM, valid);
                    if (valid) {
                        int bin = (bits >> shift) & 0xFF;
                        unsigned peers = __match_any_sync(act, bin);
                        if ((int)__ffs(peers) - 1 == lane)
                            atomicAdd(&s_hist[w][bin], __popc(peers));
                    }
                }
            }
            __syncwarp();
            int loc[8], sum = 0;
#pragma unroll
            for (int t = 0; t < 8; t++) { loc[t] = sum; sum += s_hist[w][lane * 8 + t]; }
            int ex = sum;
#pragma unroll
            for (int o = 1; o < 32; o <<= 1) {
                int tv = __shfl_up_sync(FULLM, ex, o);
                if (lane >= o) ex += tv;
            }
            ex -= sum;
            int found = 999, cbf = 0;
#pragma unroll
            for (int t = 0; t < 8; t++) {
                int cb = ex + loc[t], ct = s_hist[w][lane * 8 + t];
                if (found == 999 && kk > cb && kk <= cb + ct) { found = lane * 8 + t; cbf = cb; }
            }
            int mf = warp_min_i(found);
            unsigned who = __ballot_sync(FULLM, found == mf);
            cbf = __shfl_sync(FULLM, cbf, __ffs(who) - 1);
            prefix |= ((unsigned)mf) << shift;
            kk -= cbf;
            __syncwarp();
        }
        const unsigned Tb = prefix;

        if (lane == 0) { s_ctr[w][0] = 0; s_ctr[w][1] = 0; }
        __syncwarp();
#pragma unroll
        for (int s = 0; s < NSPLIT; s++) {
            for (int base = 0; base < c[s]; base += 32) {
                int i = base + lane;
                bool valid = (i < c[s]);
                uint2 e = valid ? seg[s][i] : make_uint2(0xffffffffu, 0u);
                if (valid && e.x < Tb) {
                    s_idx[w][atomicAdd(&s_ctr[w][0], 1)] = (int)e.y;
                } else if (valid && e.x == Tb) {
                    int p = atomicAdd(&s_ctr[w][1], 1);
                    if (p < 64) s_tie[w][p] = (int)e.y;
                }
            }
        }
        __syncwarp();
        const int nout = s_ctr[w][0];
        const int tc = min(s_ctr[w][1], 64);
        const int need = KNN - nout;
        for (int r = 0; r < need; r++) {
            int v0 = (lane < tc) ? s_tie[w][lane] : 0x7fffffff;
            int v1 = (lane + 32 < tc) ? s_tie[w][lane + 32] : 0x7fffffff;
            int mv = warp_min_i(min(v0, v1));
            if (v0 == mv && lane < tc) s_tie[w][lane] = 0x7fffffff;
            else if (v1 == mv && lane + 32 < tc) s_tie[w][lane + 32] = 0x7fffffff;
            if (lane == 0) s_idx[w][nout + r] = mv;
            __syncwarp();
        }
    }
    __syncwarp();

    // ---------- attention ----------
    const float4* qf4 = (const float4*)(qf + (size_t)q * CDIM);
    const float4 qa = qf4[lane], qb = qf4[32 + lane];

    // QK^T: 25 groups of 4 rows (8 LDG.128 in flight)
    for (int gr = 0; gr < 25; gr++) {
        const int4 id = *(const int4*)&s_idx[w][gr * 4];
        const float4* k0 = (const float4*)(kf + (size_t)id.x * CDIM);
        const float4* k1 = (const float4*)(kf + (size_t)id.y * CDIM);
        const float4* k2 = (const float4*)(kf + (size_t)id.z * CDIM);
        const float4* k3 = (const float4*)(kf + (size_t)id.w * CDIM);
        float4 a0 = k0[lane], b0 = k0[32 + lane];
        float4 a1 = k1[lane], b1 = k1[32 + lane];
        float4 a2 = k2[lane], b2 = k2[32 + lane];
        float4 a3 = k3[lane], b3 = k3[32 + lane];
        float s0 = qa.x * a0.x, s1 = qa.x * a1.x, s2 = qa.x * a2.x, s3 = qa.x * a3.x;
        s0 = fmaf(qa.y, a0.y, s0); s1 = fmaf(qa.y, a1.y, s1); s2 = fmaf(qa.y, a2.y, s2); s3 = fmaf(qa.y, a3.y, s3);
        s0 = fmaf(qa.z, a0.z, s0); s1 = fmaf(qa.z, a1.z, s1); s2 = fmaf(qa.z, a2.z, s2); s3 = fmaf(qa.z, a3.z, s3);
        s0 = fmaf(qa.w, a0.w, s0); s1 = fmaf(qa.w, a1.w, s1); s2 = fmaf(qa.w, a2.w, s2); s3 = fmaf(qa.w, a3.w, s3);
        s0 = fmaf(qb.x, b0.x, s0); s1 = fmaf(qb.x, b1.x, s1); s2 = fmaf(qb.x, b2.x, s2); s3 = fmaf(qb.x, b3.x, s3);
        s0 = fmaf(qb.y, b0.y, s0); s1 = fmaf(qb.y, b1.y, s1); s2 = fmaf(qb.y, b2.y, s2); s3 = fmaf(qb.y, b3.y, s3);
        s0 = fmaf(qb.z, b0.z, s0); s1 = fmaf(qb.z, b1.z, s1); s2 = fmaf(qb.z, b2.z, s2); s3 = fmaf(qb.z, b3.z, s3);
        s0 = fmaf(qb.w, b0.w, s0); s1 = fmaf(qb.w, b1.w, s1); s2 = fmaf(qb.w, b2.w, s2); s3 = fmaf(qb.w, b3.w, s3);
#pragma unroll
        for (int o = 16; o; o >>= 1) {
            s0 += __shfl_xor_sync(FULLM, s0, o);
            s1 += __shfl_xor_sync(FULLM, s1, o);
            s2 += __shfl_xor_sync(FULLM, s2, o);
            s3 += __shfl_xor_sync(FULLM, s3, o);
        }
        if (lane == 0)
            *(float4*)&s_p[w][gr * 4] =
                make_float4(s0 * 0.0625f, s1 * 0.0625f, s2 * 0.0625f, s3 * 0.0625f);
    }
    __syncwarp();

    // softmax within the warp
    float l0 = s_p[w][lane], l1 = s_p[w][lane + 32], l2 = s_p[w][lane + 64];
    float l3 = (lane < 4) ? s_p[w][lane + 96] : -CUDART_INF_F;
    float mx = warp_max_f(fmaxf(fmaxf(l0, l1), fmaxf(l2, l3)));
    float e0 = __expf(l0 - mx), e1 = __expf(l1 - mx), e2 = __expf(l2 - mx);
    float e3 = (lane < 4) ? __expf(l3 - mx) : 0.f;
    float sm = warp_sum_f((e0 + e1) + (e2 + e3));
    s_p[w][lane] = e0; s_p[w][lane + 32] = e1; s_p[w][lane + 64] = e2;
    if (lane < 4) s_p[w][lane + 96] = e3;
    const float sc = 2.f / sm;   // res fully overwritten by x: y = 2x; fold 1/sum
    __syncwarp();

    // PV: 2 chains x 4 rows per group
    float4 A0 = make_float4(0.f, 0.f, 0.f, 0.f), B0 = A0, A1 = A0, B1 = A0;
    for (int gr = 0; gr < 25; gr++) {
        const int4 id = *(const int4*)&s_idx[w][gr * 4];
        const float4 p4 = *(const float4*)&s_p[w][gr * 4];
        const float4* v0 = (const float4*)(vf + (size_t)id.x * CDIM);
        const float4* v1 = (const float4*)(vf + (size_t)id.y * CDIM);
        const float4* v2 = (const float4*)(vf + (size_t)id.z * CDIM);
        const float4* v3 = (const float4*)(vf + (size_t)id.w * CDIM);
        float4 va0 = v0[lane], vb0 = v0[32 + lane];
        float4 va1 = v1[lane], vb1 = v1[32 + lane];
        float4 va2 = v2[lane], vb2 = v2[32 + lane];
        float4 va3 = v3[lane], vb3 = v3[32 + lane];
        A0.x = fmaf(p4.x, va0.x, A0.x); A0.y = fmaf(p4.x, va0.y, A0.y);
        A0.z = fmaf(p4.x, va0.z, A0.z); A0.w = fmaf(p4.x, va0.w, A0.w);
        B0.x = fmaf(p4.x, vb0.x, B0.x); B0.y = fmaf(p4.x, vb0.y, B0.y);
        B0.z = fmaf(p4.x, vb0.z, B0.z); B0.w = fmaf(p4.x, vb0.w, B0.w);
        A1.x = fmaf(p4.y, va1.x, A1.x); A1.y = fmaf(p4.y, va1.y, A1.y);
        A1.z = fmaf(p4.y, va1.z, A1.z); A1.w = fmaf(p4.y, va1.w, A1.w);
        B1.x = fmaf(p4.y, vb1.x, B1.x); B1.y = fmaf(p4.y, vb1.y, B1.y);
        B1.z = fmaf(p4.y, vb1.z, B1.z); B1.w = fmaf(p4.y, vb1.w, B1.w);
        A0.x = fmaf(p4.z, va2.x, A0.x); A0.y = fmaf(p4.z, va2.y, A0.y);
        A0.z = fmaf(p4.z, va2.z, A0.z); A0.w = fmaf(p4.z, va2.w, A0.w);
        B0.x = fmaf(p4.z, vb2.x, B0.x); B0.y = fmaf(p4.z, vb2.y, B0.y);
        B0.z = fmaf(p4.z, vb2.z, B0.z); B0.w = fmaf(p4.z, vb2.w, B0.w);
        A1.x = fmaf(p4.w, va3.x, A1.x); A1.y = fmaf(p4.w, va3.y, A1.y);
        A1.z = fmaf(p4.w, va3.z, A1.z); A1.w = fmaf(p4.w, va3.w, A1.w);
        B1.x = fmaf(p4.w, vb3.x, B1.x); B1.y = fmaf(p4.w, vb3.y, B1.y);
        B1.z = fmaf(p4.w, vb3.z, B1.z); B1.w = fmaf(p4.w, vb3.w, B1.w);
    }
    float4 A = make_float4((A0.x + A1.x) * sc, (A0.y + A1.y) * sc,
                           (A0.z + A1.z) * sc, (A0.w + A1.w) * sc);
    float4 B = make_float4((B0.x + B1.x) * sc, (B0.y + B1.y) * sc,
                           (B0.z + B1.z) * sc, (B0.w + B1.w) * sc);

    // LayerNorm within the warp
    float s = ((A.x + A.y) + (A.z + A.w)) + ((B.x + B.y) + (B.z + B.w));
    const float mean = warp_sum_f(s) * (1.f / CDIM);
    float dAx = A.x - mean, dAy = A.y - mean, dAz = A.z - mean, dAw = A.w - mean;
    float dBx = B.x - mean, dBy = B.y - mean, dBz = B.z - mean, dBw = B.w - mean;
    float s2 = ((dAx * dAx + dAy * dAy) + (dAz * dAz + dAw * dAw))
             + ((dBx * dBx + dBy * dBy) + (dBz * dBz + dBw * dBw));
    const float rstd = rsqrtf(warp_sum_f(s2) * (1.f / CDIM) + 1e-5f);

    const float4* g4 = (const float4*)gamma;
    const float4* b4 = (const float4*)beta;
    float4 ga = g4[lane], gb = g4[32 + lane];
    float4 ba = b4[lane], bb = b4[32 + lane];
    float4* o4 = (float4*)(out + (size_t)q * CDIM);
    o4[lane] = make_float4(fmaf(dAx * rstd, ga.x, ba.x),
                           fmaf(dAy * rstd, ga.y, ba.y),
                           fmaf(dAz * rstd, ga.z, ba.z),
                           fmaf(dAw * rstd, ga.w, ba.w));
    o4[32 + lane] = make_float4(fmaf(dBx * rstd, gb.x, bb.x),
                                fmaf(dBy * rstd, gb.y, bb.y),
                                fmaf(dBz * rstd, gb.z, bb.z),
                                fmaf(dBw * rstd, gb.w, bb.w));
}

// ---------------- launch ----------------
extern "C" void kernel_launch(void* const* d_in, const int* in_sizes, int n_in,
                              void* d_out, int out_size) {
    (void)in_sizes; (void)n_in; (void)out_size;
    const float* qf    = (const float*)d_in[1];
    const float* kf    = (const float*)d_in[2];
    const float* vf    = (const float*)d_in[3];
    const float* qpos  = (const float*)d_in[4];
    const float* kpos  = (const float*)d_in[5];
    const float* gamma = (const float*)d_in[6];
    const float* beta  = (const float*)d_in[7];

    knn_thr<<<NQ / 8, 256>>>(qpos, kpos);
    knn_scan<<<dim3(NQ / (WPB * QPW), NSPLIT), 32 * WPB>>>(qpos, kpos);
    attn_ln<<<NQ / AW, 32 * AW>>>(qf, kf, vf, gamma, beta, (float*)d_out);
}

// round 10
// speedup vs baseline: 2.0548x; 1.0402x over previous
#include <cuda_runtime.h>
#include <math_constants.h>

#define NQ     4096
#define NKV    32768
#define CDIM   256
#define KNN    100
#define NSPLIT 8
#define RANGE  (NKV / NSPLIT)     // 4096
#define TILE   1024               // scan tile (16KB smem)
#define TTILE  1024               // thr-kernel tile (16KB smem)
#define CAPS   768                // per (query,split) segment capacity
#define QPW    4
#define WPB    4
#define AW     4                  // warps (queries) per block in attn
#define NCMAX  128                // compacted survivor cap in attn select
#define FULLM  0xffffffffu

// ---------------- static scratch ----------------
__device__ uint2 g_buf[(size_t)NQ * NSPLIT * CAPS];  // {d2 bits (>=0), kv idx}
__device__ int   g_cnt[NQ * NSPLIT];
__device__ float g_thr[NQ];

// ---------------- helpers ----------------
__device__ __forceinline__ int warp_sum_i(int v) {
#pragma unroll
    for (int o = 16; o; o >>= 1) v += __shfl_xor_sync(FULLM, v, o);
    return v;
}
__device__ __forceinline__ float warp_sum_f(float v) {
#pragma unroll
    for (int o = 16; o; o >>= 1) v += __shfl_xor_sync(FULLM, v, o);
    return v;
}
__device__ __forceinline__ float warp_max_f(float v) {
#pragma unroll
    for (int o = 16; o; o >>= 1) v = fmaxf(v, __shfl_xor_sync(FULLM, v, o));
    return v;
}
__device__ __forceinline__ int warp_min_i(int v) {
#pragma unroll
    for (int o = 16; o; o >>= 1) v = min(v, __shfl_xor_sync(FULLM, v, o));
    return v;
}

// ================= kernel 0: per-query safe threshold =================
// Warp per query (8/block). Sample = first 4096 kv points (4 x 1024 tiles,
// 16KB smem -> ~2x occupancy vs 33KB). Per-lane sorted-4 minima ->
// kth(k=100) of the 128 stash values; stash/sample are population subsets so
// thr >= true global 100th: SAFE admit filter.
__global__ void __launch_bounds__(256) knn_thr(
    const float* __restrict__ qpos, const float* __restrict__ kpos)
{
    __shared__ float4 s_tile[TTILE];
    const int tid = threadIdx.x, lane = tid & 31, w = tid >> 5;
    const int q = blockIdx.x * 8 + w;

    const float qx = qpos[3 * q], qy = qpos[3 * q + 1], qz = qpos[3 * q + 2];
    const float c0 = fmaf(qx, qx, fmaf(qy, qy, qz * qz));
    const float ax = -2.f * qx, ay = -2.f * qy, az = -2.f * qz;

    float m0 = CUDART_INF_F, m1 = CUDART_INF_F, m2 = CUDART_INF_F, m3 = CUDART_INF_F;

#pragma unroll
    for (int pass = 0; pass < 4; pass++) {
        __syncthreads();
        for (int i = tid; i < TTILE; i += 256) {
            int g = pass * TTILE + i;
            float x = kpos[3 * g], y = kpos[3 * g + 1], z = kpos[3 * g + 2];
            s_tile[i] = make_float4(x, y, z, fmaf(x, x, fmaf(y, y, z * z)));
        }
        __syncthreads();
        for (int i = lane; i < TTILE; i += 32) {
            float4 kp = s_tile[i];
            float d = fmaf(ax, kp.x, c0 + kp.w);
            d = fmaf(ay, kp.y, d);
            d = fmaf(az, kp.z, d);
            d = fmaxf(d, 0.f);
            float t0 = fminf(m0, d), t1 = fmaxf(m0, d); m0 = t0;
            float t2 = fminf(m1, t1), t3 = fmaxf(m1, t1); m1 = t2;
            float t4 = fminf(m2, t3), t5 = fmaxf(m2, t3); m2 = t4;
            m3 = fminf(m3, t5);
        }
    }

    unsigned lo = 0u, hi = 0x7f800000u;
#pragma unroll
    for (int it = 0; it < 24; it++) {
        unsigned mid = lo + ((hi - lo) >> 1);
        int c = (__float_as_uint(m0) <= mid) + (__float_as_uint(m1) <= mid)
              + (__float_as_uint(m2) <= mid) + (__float_as_uint(m3) <= mid);
        c = warp_sum_i(c);
        if (c >= KNN) hi = mid; else lo = mid + 1u;
    }
    if (lane == 0) g_thr[q] = __uint_as_float(hi);
}

// ================= kernel 1: candidate scan (KV-split x8) =================
// Hot loop: 3 FMA + compare; ballot result is warp-uniform so `if (m)` skips
// the append bookkeeping entirely on empty steps (~40% of them).
__global__ void __launch_bounds__(32 * WPB, 8) knn_scan(
    const float* __restrict__ qpos, const float* __restrict__ kpos)
{
    __shared__ float4 s_tile[TILE];

    const int tid = threadIdx.x, lane = tid & 31, warp = tid >> 5;
    const int qbase = blockIdx.x * (WPB * QPW) + warp * QPW;
    const int split = blockIdx.y;
    const int kbase = split * RANGE;
    const unsigned lt = (1u << lane) - 1u;

    float ax[QPW], ay[QPW], az[QPW], c0[QPW], tj[QPW];
    int cnt[QPW];
#pragma unroll
    for (int j = 0; j < QPW; j++) {
        int q = qbase + j;
        float qx = qpos[3 * q], qy = qpos[3 * q + 1], qz = qpos[3 * q + 2];
        c0[j] = fmaf(qx, qx, fmaf(qy, qy, qz * qz));
        ax[j] = -2.f * qx; ay[j] = -2.f * qy; az[j] = -2.f * qz;
        // bump covers FMA-order rounding diffs between thr/scan kernels
        tj[j] = g_thr[q] * 1.000002f - c0[j];
        cnt[j] = 0;
    }

    uint2* seg[QPW];
#pragma unroll
    for (int j = 0; j < QPW; j++)
        seg[j] = g_buf + ((size_t)(qbase + j) * NSPLIT + split) * CAPS;

    for (int t0 = 0; t0 < RANGE; t0 += TILE) {
        __syncthreads();
        for (int i = tid; i < TILE; i += 32 * WPB) {
            int g = kbase + t0 + i;
            float x = kpos[3 * g], y = kpos[3 * g + 1], z = kpos[3 * g + 2];
            s_tile[i] = make_float4(x, y, z, fmaf(x, x, fmaf(y, y, z * z)));
        }
        __syncthreads();
        for (int i = lane; i < TILE; i += 32) {
            float4 kp = s_tile[i];
#pragma unroll
            for (int j = 0; j < QPW; j++) {
                float dd = fmaf(ax[j], kp.x, kp.w);
                dd = fmaf(ay[j], kp.y, dd);
                dd = fmaf(az[j], kp.z, dd);
                bool p = (dd <= tj[j]);
                unsigned m = __ballot_sync(FULLM, p);
                if (m) {                       // warp-uniform branch
                    int pos = cnt[j] + __popc(m & lt);
                    if (p && pos < CAPS)
                        seg[j][pos] = make_uint2(__float_as_uint(fmaxf(dd + c0[j], 0.f)),
                                                 (unsigned)(kbase + t0 + i));
                    cnt[j] += __popc(m);
                }
            }
        }
    }
    if (lane == 0) {
#pragma unroll
        for (int j = 0; j < QPW; j++)
            g_cnt[(qbase + j) * NSPLIT + split] = min(cnt[j], CAPS);
    }
}

// ================= kernel 2: fused select + attention + LN, warp/query =====
__global__ void __launch_bounds__(32 * AW) attn_ln(
    const float* __restrict__ qf, const float* __restrict__ kf,
    const float* __restrict__ vf, const float* __restrict__ gamma,
    const float* __restrict__ beta, float* __restrict__ out)
{
    __shared__ int   s_idx[AW][100];
    __shared__ float s_p[AW][104];
    __shared__ int   s_hist[AW][257];
    __shared__ uint2 s_cand[AW][NCMAX];
    __shared__ int   s_tie[AW][64];

    const int lane = threadIdx.x & 31, w = threadIdx.x >> 5;
    const int q = blockIdx.x * AW + w;
    const unsigned lt = (1u << lane) - 1u;

    // ---------- exact top-100 select (per warp) ----------
    {
        const uint2* seg[NSPLIT];
        int c[NSPLIT];
#pragma unroll
        for (int s = 0; s < NSPLIT; s++) {
            seg[s] = g_buf + ((size_t)q * NSPLIT + s) * CAPS;
            c[s] = g_cnt[q * NSPLIT + s];
        }

        // -- rounds 1-2: 8-bit histograms over gmem (top 16 bits of 100th) --
        unsigned prefix = 0;
        int kk = KNN;
#pragma unroll
        for (int shift = 24; shift >= 16; shift -= 8) {
            for (int b = lane; b < 256; b += 32) s_hist[w][b] = 0;
            __syncwarp();
            const unsigned himask = (shift == 24) ? 0u : 0xff000000u;
#pragma unroll
            for (int s = 0; s < NSPLIT; s++) {
                for (int base = 0; base < c[s]; base += 32) {
                    int i = base + lane;
                    bool valid = (i < c[s]);
                    unsigned bits = valid ? seg[s][i].x : 0u;
                    valid = valid && ((bits & himask) == prefix);
                    unsigned act = __ballot_sync(FULLM, valid);
                    if (valid) {
                        int bin = (bits >> shift) & 0xFF;
                        unsigned peers = __match_any_sync(act, bin);
                        if ((int)__ffs(peers) - 1 == lane)
                            atomicAdd(&s_hist[w][bin], __popc(peers));
                    }
                }
            }
            __syncwarp();
            int loc[8], sum = 0;
#pragma unroll
            for (int t = 0; t < 8; t++) { loc[t] = sum; sum += s_hist[w][lane * 8 + t]; }
            int ex = sum;
#pragma unroll
            for (int o = 1; o < 32; o <<= 1) {
                int tv = __shfl_up_sync(FULLM, ex, o);
                if (lane >= o) ex += tv;
            }
            ex -= sum;
            int found = 999, cbf = 0;
#pragma unroll
            for (int t = 0; t < 8; t++) {
                int cb = ex + loc[t], ct = s_hist[w][lane * 8 + t];
                if (found == 999 && kk > cb && kk <= cb + ct) { found = lane * 8 + t; cbf = cb; }
            }
            int mf = warp_min_i(found);
            unsigned who = __ballot_sync(FULLM, found == mf);
            cbf = __shfl_sync(FULLM, cbf, __ffs(who) - 1);
            prefix |= ((unsigned)mf) << shift;
            kk -= cbf;
            __syncwarp();
        }

        // -- compact survivors (top16 == prefix16) into smem --
        int ncand = 0;
#pragma unroll
        for (int s = 0; s < NSPLIT; s++) {
            for (int base = 0; base < c[s]; base += 32) {
                int i = base + lane;
                bool valid = (i < c[s]);
                uint2 e = valid ? seg[s][i] : make_uint2(0u, 0u);
                bool hit = valid && ((e.x & 0xffff0000u) == prefix);
                unsigned mh = __ballot_sync(FULLM, hit);
                if (mh) {
                    int pos = ncand + __popc(mh & lt);
                    if (hit && pos < NCMAX) s_cand[w][pos] = e;
                    ncand += __popc(mh);
                }
            }
        }
        __syncwarp();

        // -- resolve low 16 bits of the 100th value --
        unsigned Tb;
        if (ncand <= NCMAX) {
            // warp binary search over <=128 smem survivors
            unsigned b0 = (lane < ncand)       ? (s_cand[w][lane].x & 0xffffu)       : 0xffffffffu;
            unsigned b1 = (lane + 32 < ncand)  ? (s_cand[w][lane + 32].x & 0xffffu)  : 0xffffffffu;
            unsigned b2 = (lane + 64 < ncand)  ? (s_cand[w][lane + 64].x & 0xffffu)  : 0xffffffffu;
            unsigned b3 = (lane + 96 < ncand)  ? (s_cand[w][lane + 96].x & 0xffffu)  : 0xffffffffu;
            unsigned lo = 0u, hi = 0xffffu;
#pragma unroll
            for (int it = 0; it < 16; it++) {
                unsigned mid = lo + ((hi - lo) >> 1);
                int cc = (b0 <= mid) + (b1 <= mid) + (b2 <= mid) + (b3 <= mid);
                cc = warp_sum_i(cc);
                if (cc >= kk) hi = mid; else lo = mid + 1u;
            }
            Tb = prefix | lo;
        } else {
            // fallback (essentially never): binary search over gmem survivors
            unsigned lo = 0u, hi = 0xffffu;
            while (lo < hi) {
                unsigned mid = lo + ((hi - lo) >> 1);
                int cc = 0;
#pragma unroll
                for (int s = 0; s < NSPLIT; s++)
                    for (int base = 0; base < c[s]; base += 32) {
                        int i = base + lane;
                        if (i < c[s]) {
                            unsigned bits = seg[s][i].x;
                            cc += ((bits & 0xffff0000u) == prefix && (bits & 0xffffu) <= mid);
                        }
                    }
                cc = warp_sum_i(cc);
                if (cc >= kk) hi = mid; else lo = mid + 1u;
            }
            Tb = prefix | lo;
        }

        // -- emit: all < Tb via ballot ordering (no atomics) --
        int nout = 0;
#pragma unroll
        for (int s = 0; s < NSPLIT; s++) {
            for (int base = 0; base < c[s]; base += 32) {
                int i = base + lane;
                bool valid = (i < c[s]);
                uint2 e = valid ? seg[s][i] : make_uint2(0xffffffffu, 0u);
                bool w1 = (e.x < Tb);
                unsigned m1 = __ballot_sync(FULLM, w1);
                if (m1) {
                    if (w1) s_idx[w][nout + __popc(m1 & lt)] = (int)e.y;
                    nout += __popc(m1);
                }
            }
        }
        // -- ties == Tb: from compacted list (fast) or gmem (fallback) --
        int ntie = 0;
        if (ncand <= NCMAX) {
            for (int base = 0; base < ncand; base += 32) {
                int i = base + lane;
                bool v = (i < ncand) && (s_cand[w][i].x == Tb);
                unsigned m2 = __ballot_sync(FULLM, v);
                if (v) {
                    int p = ntie + __popc(m2 & lt);
                    if (p < 64) s_tie[w][p] = (int)s_cand[w][i].y;
                }
                ntie += __popc(m2);
            }
        } else {
#pragma unroll
            for (int s = 0; s < NSPLIT; s++)
                for (int base = 0; base < c[s]; base += 32) {
                    int i = base + lane;
                    bool v = (i < c[s]) && (seg[s][i].x == Tb);
                    unsigned m2 = __ballot_sync(FULLM, v);
                    if (v) {
                        int p = ntie + __popc(m2 & lt);
                        if (p < 64) s_tie[w][p] = (int)seg[s][i].y;
                    }
                    ntie += __popc(m2);
                }
        }
        __syncwarp();
        const int tc = min(ntie, 64);
        const int need = KNN - nout;
        for (int r = 0; r < need; r++) {
            int v0 = (lane < tc) ? s_tie[w][lane] : 0x7fffffff;
            int v1 = (lane + 32 < tc) ? s_tie[w][lane + 32] : 0x7fffffff;
            int mv = warp_min_i(min(v0, v1));
            if (v0 == mv && lane < tc) s_tie[w][lane] = 0x7fffffff;
            else if (v1 == mv && lane + 32 < tc) s_tie[w][lane + 32] = 0x7fffffff;
            if (lane == 0) s_idx[w][nout + r] = mv;
            __syncwarp();
        }
    }
    __syncwarp();

    // ---------- attention ----------
    const float4* qf4 = (const float4*)(qf + (size_t)q * CDIM);
    const float4 qa = qf4[lane], qb = qf4[32 + lane];

    // QK^T: 25 groups of 4 rows (8 LDG.128 in flight)
    for (int gr = 0; gr < 25; gr++) {
        const int4 id = *(const int4*)&s_idx[w][gr * 4];
        const float4* k0 = (const float4*)(kf + (size_t)id.x * CDIM);
        const float4* k1 = (const float4*)(kf + (size_t)id.y * CDIM);
        const float4* k2 = (const float4*)(kf + (size_t)id.z * CDIM);
        const float4* k3 = (const float4*)(kf + (size_t)id.w * CDIM);
        float4 a0 = k0[lane], b0 = k0[32 + lane];
        float4 a1 = k1[lane], b1 = k1[32 + lane];
        float4 a2 = k2[lane], b2 = k2[32 + lane];
        float4 a3 = k3[lane], b3 = k3[32 + lane];
        float s0 = qa.x * a0.x, s1 = qa.x * a1.x, s2 = qa.x * a2.x, s3 = qa.x * a3.x;
        s0 = fmaf(qa.y, a0.y, s0); s1 = fmaf(qa.y, a1.y, s1); s2 = fmaf(qa.y, a2.y, s2); s3 = fmaf(qa.y, a3.y, s3);
        s0 = fmaf(qa.z, a0.z, s0); s1 = fmaf(qa.z, a1.z, s1); s2 = fmaf(qa.z, a2.z, s2); s3 = fmaf(qa.z, a3.z, s3);
        s0 = fmaf(qa.w, a0.w, s0); s1 = fmaf(qa.w, a1.w, s1); s2 = fmaf(qa.w, a2.w, s2); s3 = fmaf(qa.w, a3.w, s3);
        s0 = fmaf(qb.x, b0.x, s0); s1 = fmaf(qb.x, b1.x, s1); s2 = fmaf(qb.x, b2.x, s2); s3 = fmaf(qb.x, b3.x, s3);
        s0 = fmaf(qb.y, b0.y, s0); s1 = fmaf(qb.y, b1.y, s1); s2 = fmaf(qb.y, b2.y, s2); s3 = fmaf(qb.y, b3.y, s3);
        s0 = fmaf(qb.z, b0.z, s0); s1 = fmaf(qb.z, b1.z, s1); s2 = fmaf(qb.z, b2.z, s2); s3 = fmaf(qb.z, b3.z, s3);
        s0 = fmaf(qb.w, b0.w, s0); s1 = fmaf(qb.w, b1.w, s1); s2 = fmaf(qb.w, b2.w, s2); s3 = fmaf(qb.w, b3.w, s3);
#pragma unroll
        for (int o = 16; o; o >>= 1) {
            s0 += __shfl_xor_sync(FULLM, s0, o);
            s1 += __shfl_xor_sync(FULLM, s1, o);
            s2 += __shfl_xor_sync(FULLM, s2, o);
            s3 += __shfl_xor_sync(FULLM, s3, o);
        }
        if (lane == 0)
            *(float4*)&s_p[w][gr * 4] =
                make_float4(s0 * 0.0625f, s1 * 0.0625f, s2 * 0.0625f, s3 * 0.0625f);
    }
    __syncwarp();

    // softmax within the warp
    float l0 = s_p[w][lane], l1 = s_p[w][lane + 32], l2 = s_p[w][lane + 64];
    float l3 = (lane < 4) ? s_p[w][lane + 96] : -CUDART_INF_F;
    float mx = warp_max_f(fmaxf(fmaxf(l0, l1), fmaxf(l2, l3)));
    float e0 = __expf(l0 - mx), e1 = __expf(l1 - mx), e2 = __expf(l2 - mx);
    float e3 = (lane < 4) ? __expf(l3 - mx) : 0.f;
    float sm = warp_sum_f((e0 + e1) + (e2 + e3));
    s_p[w][lane] = e0; s_p[w][lane + 32] = e1; s_p[w][lane + 64] = e2;
    if (lane < 4) s_p[w][lane + 96] = e3;
    const float sc = 2.f / sm;   // res fully overwritten by x: y = 2x; fold 1/sum
    __syncwarp();

    // PV: 2 chains x 4 rows per group
    float4 A0 = make_float4(0.f, 0.f, 0.f, 0.f), B0 = A0, A1 = A0, B1 = A0;
    for (int gr = 0; gr < 25; gr++) {
        const int4 id = *(const int4*)&s_idx[w][gr * 4];
        const float4 p4 = *(const float4*)&s_p[w][gr * 4];
        const float4* v0 = (const float4*)(vf + (size_t)id.x * CDIM);
        const float4* v1 = (const float4*)(vf + (size_t)id.y * CDIM);
        const float4* v2 = (const float4*)(vf + (size_t)id.z * CDIM);
        const float4* v3 = (const float4*)(vf + (size_t)id.w * CDIM);
        float4 va0 = v0[lane], vb0 = v0[32 + lane];
        float4 va1 = v1[lane], vb1 = v1[32 + lane];
        float4 va2 = v2[lane], vb2 = v2[32 + lane];
        float4 va3 = v3[lane], vb3 = v3[32 + lane];
        A0.x = fmaf(p4.x, va0.x, A0.x); A0.y = fmaf(p4.x, va0.y, A0.y);
        A0.z = fmaf(p4.x, va0.z, A0.z); A0.w = fmaf(p4.x, va0.w, A0.w);
        B0.x = fmaf(p4.x, vb0.x, B0.x); B0.y = fmaf(p4.x, vb0.y, B0.y);
        B0.z = fmaf(p4.x, vb0.z, B0.z); B0.w = fmaf(p4.x, vb0.w, B0.w);
        A1.x = fmaf(p4.y, va1.x, A1.x); A1.y = fmaf(p4.y, va1.y, A1.y);
        A1.z = fmaf(p4.y, va1.z, A1.z); A1.w = fmaf(p4.y, va1.w, A1.w);
        B1.x = fmaf(p4.y, vb1.x, B1.x); B1.y = fmaf(p4.y, vb1.y, B1.y);
        B1.z = fmaf(p4.y, vb1.z, B1.z); B1.w = fmaf(p4.y, vb1.w, B1.w);
        A0.x = fmaf(p4.z, va2.x, A0.x); A0.y = fmaf(p4.z, va2.y, A0.y);
        A0.z = fmaf(p4.z, va2.z, A0.z); A0.w = fmaf(p4.z, va2.w, A0.w);
        B0.x = fmaf(p4.z, vb2.x, B0.x); B0.y = fmaf(p4.z, vb2.y, B0.y);
        B0.z = fmaf(p4.z, vb2.z, B0.z); B0.w = fmaf(p4.z, vb2.w, B0.w);
        A1.x = fmaf(p4.w, va3.x, A1.x); A1.y = fmaf(p4.w, va3.y, A1.y);
        A1.z = fmaf(p4.w, va3.z, A1.z); A1.w = fmaf(p4.w, va3.w, A1.w);
        B1.x = fmaf(p4.w, vb3.x, B1.x); B1.y = fmaf(p4.w, vb3.y, B1.y);
        B1.z = fmaf(p4.w, vb3.z, B1.z); B1.w = fmaf(p4.w, vb3.w, B1.w);
    }
    float4 A = make_float4((A0.x + A1.x) * sc, (A0.y + A1.y) * sc,
                           (A0.z + A1.z) * sc, (A0.w + A1.w) * sc);
    float4 B = make_float4((B0.x + B1.x) * sc, (B0.y + B1.y) * sc,
                           (B0.z + B1.z) * sc, (B0.w + B1.w) * sc);

    // LayerNorm within the warp
    float s = ((A.x + A.y) + (A.z + A.w)) + ((B.x + B.y) + (B.z + B.w));
    const float mean = warp_sum_f(s) * (1.f / CDIM);
    float dAx = A.x - mean, dAy = A.y - mean, dAz = A.z - mean, dAw = A.w - mean;
    float dBx = B.x - mean, dBy = B.y - mean, dBz = B.z - mean, dBw = B.w - mean;
    float s2 = ((dAx * dAx + dAy * dAy) + (dAz * dAz + dAw * dAw))
             + ((dBx * dBx + dBy * dBy) + (dBz * dBz + dBw * dBw));
    const float rstd = rsqrtf(warp_sum_f(s2) * (1.f / CDIM) + 1e-5f);

    const float4* g4 = (const float4*)gamma;
    const float4* b4 = (const float4*)beta;
    float4 ga = g4[lane], gb = g4[32 + lane];
    float4 ba = b4[lane], bb = b4[32 + lane];
    float4* o4 = (float4*)(out + (size_t)q * CDIM);
    o4[lane] = make_float4(fmaf(dAx * rstd, ga.x, ba.x),
                           fmaf(dAy * rstd, ga.y, ba.y),
                           fmaf(dAz * rstd, ga.z, ba.z),
                           fmaf(dAw * rstd, ga.w, ba.w));
    o4[32 + lane] = make_float4(fmaf(dBx * rstd, gb.x, bb.x),
                                fmaf(dBy * rstd, gb.y, bb.y),
                                fmaf(dBz * rstd, gb.z, bb.z),
                                fmaf(dBw * rstd, gb.w, bb.w));
}

// ---------------- launch ----------------
extern "C" void kernel_launch(void* const* d_in, const int* in_sizes, int n_in,
                              void* d_out, int out_size) {
    (void)in_sizes; (void)n_in; (void)out_size;
    const float* qf    = (const float*)d_in[1];
    const float* kf    = (const float*)d_in[2];
    const float* vf    = (const float*)d_in[3];
    const float* qpos  = (const float*)d_in[4];
    const float* kpos  = (const float*)d_in[5];
    const float* gamma = (const float*)d_in[6];
    const float* beta  = (const float*)d_in[7];

    knn_thr<<<NQ / 8, 256>>>(qpos, kpos);
    knn_scan<<<dim3(NQ / (WPB * QPW), NSPLIT), 32 * WPB>>>(qpos, kpos);
    attn_ln<<<NQ / AW, 32 * AW>>>(qf, kf, vf, gamma, beta, (float*)d_out);
}

// round 11
// speedup vs baseline: 2.1821x; 1.0620x over previous
#include <cuda_runtime.h>
#include <math_constants.h>

#define NQ     4096
#define NKV    32768
#define CDIM   256
#define KNN    100
#define NSPLIT 8
#define RANGE  (NKV / NSPLIT)     // 4096
#define TILE   1024               // scan tile (16KB smem)
#define CAPS   768                // per (query,split) segment capacity
#define QPW    4
#define WPB    4
#define AW     4                  // warps (queries) per block in attn
#define NCMAX  128                // compacted survivor cap in attn select
#define FULLM  0xffffffffu

// ---------------- static scratch ----------------
__device__ uint2 g_buf[(size_t)NQ * NSPLIT * CAPS];  // {d2 bits (>=0), kv idx}
__device__ int   g_cnt[NQ * NSPLIT];
__device__ float g_thr[NQ];

// ---------------- helpers ----------------
__device__ __forceinline__ int warp_sum_i(int v) {
#pragma unroll
    for (int o = 16; o; o >>= 1) v += __shfl_xor_sync(FULLM, v, o);
    return v;
}
__device__ __forceinline__ float warp_sum_f(float v) {
#pragma unroll
    for (int o = 16; o; o >>= 1) v += __shfl_xor_sync(FULLM, v, o);
    return v;
}
__device__ __forceinline__ float warp_max_f(float v) {
#pragma unroll
    for (int o = 16; o; o >>= 1) v = fmaxf(v, __shfl_xor_sync(FULLM, v, o));
    return v;
}
__device__ __forceinline__ int warp_min_i(int v) {
#pragma unroll
    for (int o = 16; o; o >>= 1) v = min(v, __shfl_xor_sync(FULLM, v, o));
    return v;
}

// sorted-4 ascending insert (7 ops, branchless)
#define INS4(M0, M1, M2, M3, D) do {                       \
    float _t1 = fmaxf(M0, D); M0 = fminf(M0, D);           \
    float _t3 = fmaxf(M1, _t1); M1 = fminf(M1, _t1);       \
    float _t5 = fmaxf(M2, _t3); M2 = fminf(M2, _t3);       \
    M3 = fminf(M3, _t5);                                   \
} while (0)

// ================= kernel 0: per-query safe threshold =================
// Warp per query (4/block), NO smem, NO barriers. Sample = first 4096 kv
// points read as 3 x LDG.128 per lane per macro-step. Two independent
// sorted-4 chains per lane (even/odd candidates) double the ILP. Distance
// uses the bit-identical op sequence to knn_scan. Threshold = kth(100) of
// the 256 stash values; stash subset of sample subset of population =>
// thr >= true global 100th: SAFE admit filter.
__global__ void __launch_bounds__(128) knn_thr(
    const float* __restrict__ qpos, const float* __restrict__ kpos)
{
    const int lane = threadIdx.x & 31, w = threadIdx.x >> 5;
    const int q = blockIdx.x * 4 + w;

    const float qx = qpos[3 * q], qy = qpos[3 * q + 1], qz = qpos[3 * q + 2];
    const float c0 = fmaf(qx, qx, fmaf(qy, qy, qz * qz));
    const float ax = -2.f * qx, ay = -2.f * qy, az = -2.f * qz;

    const float4* kp4 = (const float4*)kpos;

    float A0 = CUDART_INF_F, A1 = A0, A2 = A0, A3 = A0;   // chain A
    float B0 = A0, B1 = A0, B2 = A0, B3 = A0;             // chain B

    for (int s = 0; s < 32; s++) {
        const int b = s * 96 + lane * 3;   // 4 candidates = 3 float4s
        const float4 f0 = __ldg(kp4 + b);
        const float4 f1 = __ldg(kp4 + b + 1);
        const float4 f2 = __ldg(kp4 + b + 2);
        // cand0=(f0.x,f0.y,f0.z) cand1=(f0.w,f1.x,f1.y)
        // cand2=(f1.z,f1.w,f2.x) cand3=(f2.y,f2.z,f2.w)
        float w0 = fmaf(f0.x, f0.x, fmaf(f0.y, f0.y, f0.z * f0.z));
        float w1 = fmaf(f0.w, f0.w, fmaf(f1.x, f1.x, f1.y * f1.y));
        float w2 = fmaf(f1.z, f1.z, fmaf(f1.w, f1.w, f2.x * f2.x));
        float w3 = fmaf(f2.y, f2.y, fmaf(f2.z, f2.z, f2.w * f2.w));
        float d0 = fmaf(ax, f0.x, w0); d0 = fmaf(ay, f0.y, d0); d0 = fmaf(az, f0.z, d0); d0 += c0;
        float d1 = fmaf(ax, f0.w, w1); d1 = fmaf(ay, f1.x, d1); d1 = fmaf(az, f1.y, d1); d1 += c0;
        float d2 = fmaf(ax, f1.z, w2); d2 = fmaf(ay, f1.w, d2); d2 = fmaf(az, f2.x, d2); d2 += c0;
        float d3 = fmaf(ax, f2.y, w3); d3 = fmaf(ay, f2.z, d3); d3 = fmaf(az, f2.w, d3); d3 += c0;
        INS4(A0, A1, A2, A3, d0);
        INS4(B0, B1, B2, B3, d1);
        INS4(A0, A1, A2, A3, d2);
        INS4(B0, B1, B2, B3, d3);
    }
    // clamp at the end (monotone -> kth of clamped == clamp of kth)
    A0 = fmaxf(A0, 0.f); A1 = fmaxf(A1, 0.f); A2 = fmaxf(A2, 0.f); A3 = fmaxf(A3, 0.f);
    B0 = fmaxf(B0, 0.f); B1 = fmaxf(B1, 0.f); B2 = fmaxf(B2, 0.f); B3 = fmaxf(B3, 0.f);

    unsigned lo = 0u, hi = 0x7f800000u;
#pragma unroll
    for (int it = 0; it < 24; it++) {
        unsigned mid = lo + ((hi - lo) >> 1);
        int c = (__float_as_uint(A0) <= mid) + (__float_as_uint(A1) <= mid)
              + (__float_as_uint(A2) <= mid) + (__float_as_uint(A3) <= mid)
              + (__float_as_uint(B0) <= mid) + (__float_as_uint(B1) <= mid)
              + (__float_as_uint(B2) <= mid) + (__float_as_uint(B3) <= mid);
        c = warp_sum_i(c);
        if (c >= KNN) hi = mid; else lo = mid + 1u;
    }
    if (lane == 0) g_thr[q] = __uint_as_float(hi);
}

// ================= kernel 1: candidate scan (KV-split x8) =================
// Hot loop: 3 FMA + compare; ballot result is warp-uniform so `if (m)` skips
// the append bookkeeping entirely on empty steps (~40% of them).
__global__ void __launch_bounds__(32 * WPB, 8) knn_scan(
    const float* __restrict__ qpos, const float* __restrict__ kpos)
{
    __shared__ float4 s_tile[TILE];

    const int tid = threadIdx.x, lane = tid & 31, warp = tid >> 5;
    const int qbase = blockIdx.x * (WPB * QPW) + warp * QPW;
    const int split = blockIdx.y;
    const int kbase = split * RANGE;
    const unsigned lt = (1u << lane) - 1u;

    float ax[QPW], ay[QPW], az[QPW], c0[QPW], tj[QPW];
    int cnt[QPW];
#pragma unroll
    for (int j = 0; j < QPW; j++) {
        int q = qbase + j;
        float qx = qpos[3 * q], qy = qpos[3 * q + 1], qz = qpos[3 * q + 2];
        c0[j] = fmaf(qx, qx, fmaf(qy, qy, qz * qz));
        ax[j] = -2.f * qx; ay[j] = -2.f * qy; az[j] = -2.f * qz;
        // bump covers FMA-order rounding diffs between thr/scan kernels
        tj[j] = g_thr[q] * 1.000004f - c0[j];
        cnt[j] = 0;
    }

    uint2* seg[QPW];
#pragma unroll
    for (int j = 0; j < QPW; j++)
        seg[j] = g_buf + ((size_t)(qbase + j) * NSPLIT + split) * CAPS;

    for (int t0 = 0; t0 < RANGE; t0 += TILE) {
        __syncthreads();
        for (int i = tid; i < TILE; i += 32 * WPB) {
            int g = kbase + t0 + i;
            float x = kpos[3 * g], y = kpos[3 * g + 1], z = kpos[3 * g + 2];
            s_tile[i] = make_float4(x, y, z, fmaf(x, x, fmaf(y, y, z * z)));
        }
        __syncthreads();
        for (int i = lane; i < TILE; i += 32) {
            float4 kp = s_tile[i];
#pragma unroll
            for (int j = 0; j < QPW; j++) {
                float dd = fmaf(ax[j], kp.x, kp.w);
                dd = fmaf(ay[j], kp.y, dd);
                dd = fmaf(az[j], kp.z, dd);
                bool p = (dd <= tj[j]);
                unsigned m = __ballot_sync(FULLM, p);
                if (m) {                       // warp-uniform branch
                    int pos = cnt[j] + __popc(m & lt);
                    if (p && pos < CAPS)
                        seg[j][pos] = make_uint2(__float_as_uint(fmaxf(dd + c0[j], 0.f)),
                                                 (unsigned)(kbase + t0 + i));
                    cnt[j] += __popc(m);
                }
            }
        }
    }
    if (lane == 0) {
#pragma unroll
        for (int j = 0; j < QPW; j++)
            g_cnt[(qbase + j) * NSPLIT + split] = min(cnt[j], CAPS);
    }
}

// ================= kernel 2: fused select + attention + LN, warp/query =====
__global__ void __launch_bounds__(32 * AW) attn_ln(
    const float* __restrict__ qf, const float* __restrict__ kf,
    const float* __restrict__ vf, const float* __restrict__ gamma,
    const float* __restrict__ beta, float* __restrict__ out)
{
    __shared__ int   s_idx[AW][100];
    __shared__ float s_p[AW][104];
    __shared__ int   s_hist[AW][257];
    __shared__ uint2 s_cand[AW][NCMAX];
    __shared__ int   s_tie[AW][64];

    const int lane = threadIdx.x & 31, w = threadIdx.x >> 5;
    const int q = blockIdx.x * AW + w;
    const unsigned lt = (1u << lane) - 1u;

    // ---------- exact top-100 select (per warp) ----------
    {
        const uint2* seg[NSPLIT];
        int c[NSPLIT];
#pragma unroll
        for (int s = 0; s < NSPLIT; s++) {
            seg[s] = g_buf + ((size_t)q * NSPLIT + s) * CAPS;
            c[s] = g_cnt[q * NSPLIT + s];
        }

        // -- rounds 1-2: 8-bit histograms over gmem (top 16 bits of 100th) --
        unsigned prefix = 0;
        int kk = KNN;
#pragma unroll
        for (int shift = 24; shift >= 16; shift -= 8) {
            for (int b = lane; b < 256; b += 32) s_hist[w][b] = 0;
            __syncwarp();
            const unsigned himask = (shift == 24) ? 0u : 0xff000000u;
#pragma unroll
            for (int s = 0; s < NSPLIT; s++) {
                for (int base = 0; base < c[s]; base += 32) {
                    int i = base + lane;
                    bool valid = (i < c[s]);
                    unsigned bits = valid ? seg[s][i].x : 0u;
                    valid = valid && ((bits & himask) == prefix);
                    unsigned act = __ballot_sync(FULLM, valid);
                    if (valid) {
                        int bin = (bits >> shift) & 0xFF;
                        unsigned peers = __match_any_sync(act, bin);
                        if ((int)__ffs(peers) - 1 == lane)
                            atomicAdd(&s_hist[w][bin], __popc(peers));
                    }
                }
            }
            __syncwarp();
            int loc[8], sum = 0;
#pragma unroll
            for (int t = 0; t < 8; t++) { loc[t] = sum; sum += s_hist[w][lane * 8 + t]; }
            int ex = sum;
#pragma unroll
            for (int o = 1; o < 32; o <<= 1) {
                int tv = __shfl_up_sync(FULLM, ex, o);
                if (lane >= o) ex += tv;
            }
            ex -= sum;
            int found = 999, cbf = 0;
#pragma unroll
            for (int t = 0; t < 8; t++) {
                int cb = ex + loc[t], ct = s_hist[w][lane * 8 + t];
                if (found == 999 && kk > cb && kk <= cb + ct) { found = lane * 8 + t; cbf = cb; }
            }
            int mf = warp_min_i(found);
            unsigned who = __ballot_sync(FULLM, found == mf);
            cbf = __shfl_sync(FULLM, cbf, __ffs(who) - 1);
            prefix |= ((unsigned)mf) << shift;
            kk -= cbf;
            __syncwarp();
        }

        // -- combined pass: emit all < prefix block; compact top16==prefix --
        // (values with top16 < prefix16 are guaranteed below the 100th; there
        //  are exactly KNN-kk of them by construction of the radix rounds)
        int nout = 0, ncand = 0;
#pragma unroll
        for (int s = 0; s < NSPLIT; s++) {
            for (int base = 0; base < c[s]; base += 32) {
                int i = base + lane;
                bool valid = (i < c[s]);
                uint2 e = valid ? seg[s][i] : make_uint2(0xffffffffu, 0u);
                bool w1 = (e.x < prefix);
                unsigned m1 = __ballot_sync(FULLM, w1);
                if (m1) {
                    if (w1) s_idx[w][nout + __popc(m1 & lt)] = (int)e.y;
                    nout += __popc(m1);
                }
                bool h = ((e.x & 0xffff0000u) == prefix);
                unsigned mh = __ballot_sync(FULLM, h);
                if (mh) {
                    int pos = ncand + __popc(mh & lt);
                    if (h && pos < NCMAX) s_cand[w][pos] = e;
                    ncand += __popc(mh);
                }
            }
        }
        __syncwarp();

        if (ncand <= NCMAX) {
            // -- low-16 bits of the 100th: warp binary search over smem --
            unsigned b0 = (lane < ncand)      ? (s_cand[w][lane].x & 0xffffu)      : 0xffffffffu;
            unsigned b1 = (lane + 32 < ncand) ? (s_cand[w][lane + 32].x & 0xffffu) : 0xffffffffu;
            unsigned b2 = (lane + 64 < ncand) ? (s_cand[w][lane + 64].x & 0xffffu) : 0xffffffffu;
            unsigned b3 = (lane + 96 < ncand) ? (s_cand[w][lane + 96].x & 0xffffu) : 0xffffffffu;
            unsigned lo = 0u, hi = 0xffffu;
#pragma unroll
            for (int it = 0; it < 16; it++) {
                unsigned mid = lo + ((hi - lo) >> 1);
                int cc = (b0 <= mid) + (b1 <= mid) + (b2 <= mid) + (b3 <= mid);
                cc = warp_sum_i(cc);
                if (cc >= kk) hi = mid; else lo = mid + 1u;
            }
            // -- emit survivors with low16 < lo (smem, segment order) --
            for (int base = 0; base < ncand; base += 32) {
                int i = base + lane;
                bool v = (i < ncand) && ((s_cand[w][i].x & 0xffffu) < lo);
                unsigned m1 = __ballot_sync(FULLM, v);
                if (m1) {
                    if (v) s_idx[w][nout + __popc(m1 & lt)] = (int)s_cand[w][i].y;
                    nout += __popc(m1);
                }
            }
            // -- ties (low16 == lo): smallest kv indices win --
            int ntie = 0;
            for (int base = 0; base < ncand; base += 32) {
                int i = base + lane;
                bool v = (i < ncand) && ((s_cand[w][i].x & 0xffffu) == lo);
                unsigned m2 = __ballot_sync(FULLM, v);
                if (v) {
                    int p = ntie + __popc(m2 & lt);
                    if (p < 64) s_tie[w][p] = (int)s_cand[w][i].y;
                }
                ntie += __popc(m2);
            }
            __syncwarp();
            const int tc = min(ntie, 64);
            const int need = KNN - nout;
            for (int r = 0; r < need; r++) {
                int v0 = (lane < tc) ? s_tie[w][lane] : 0x7fffffff;
                int v1 = (lane + 32 < tc) ? s_tie[w][lane + 32] : 0x7fffffff;
                int mv = warp_min_i(min(v0, v1));
                if (v0 == mv && lane < tc) s_tie[w][lane] = 0x7fffffff;
                else if (v1 == mv && lane + 32 < tc) s_tie[w][lane + 32] = 0x7fffffff;
                if (lane == 0) s_idx[w][nout + r] = mv;
                __syncwarp();
            }
        } else {
            // -- fallback (essentially never): full gmem resolution --
            unsigned lo = 0u, hi = 0xffffu;
            while (lo < hi) {
                unsigned mid = lo + ((hi - lo) >> 1);
                int cc = 0;
#pragma unroll
                for (int s = 0; s < NSPLIT; s++)
                    for (int base = 0; base < c[s]; base += 32) {
                        int i = base + lane;
                        if (i < c[s]) {
                            unsigned bits = seg[s][i].x;
                            cc += ((bits & 0xffff0000u) == prefix && (bits & 0xffffu) <= mid);
                        }
                    }
                cc = warp_sum_i(cc);
                if (cc >= kk) hi = mid; else lo = mid + 1u;
            }
            const unsigned Tb = prefix | lo;
            nout = 0;
#pragma unroll
            for (int s = 0; s < NSPLIT; s++) {
                for (int base = 0; base < c[s]; base += 32) {
                    int i = base + lane;
                    bool valid = (i < c[s]);
                    uint2 e = valid ? seg[s][i] : make_uint2(0xffffffffu, 0u);
                    bool w1 = (e.x < Tb);
                    unsigned m1 = __ballot_sync(FULLM, w1);
                    if (w1) s_idx[w][nout + __popc(m1 & lt)] = (int)e.y;
                    nout += __popc(m1);
                }
            }
            int ntie = 0;
#pragma unroll
            for (int s = 0; s < NSPLIT; s++)
                for (int base = 0; base < c[s]; base += 32) {
                    int i = base + lane;
                    bool v = (i < c[s]) && (seg[s][i].x == Tb);
                    unsigned m2 = __ballot_sync(FULLM, v);
                    if (v) {
                        int p = ntie + __popc(m2 & lt);
                        if (p < 64) s_tie[w][p] = (int)seg[s][i].y;
                    }
                    ntie += __popc(m2);
                }
            __syncwarp();
            const int tc = min(ntie, 64);
            const int need = KNN - nout;
            for (int r = 0; r < need; r++) {
                int v0 = (lane < tc) ? s_tie[w][lane] : 0x7fffffff;
                int v1 = (lane + 32 < tc) ? s_tie[w][lane + 32] : 0x7fffffff;
                int mv = warp_min_i(min(v0, v1));
                if (v0 == mv && lane < tc) s_tie[w][lane] = 0x7fffffff;
                else if (v1 == mv && lane + 32 < tc) s_tie[w][lane + 32] = 0x7fffffff;
                if (lane == 0) s_idx[w][nout + r] = mv;
                __syncwarp();
            }
        }
    }
    __syncwarp();

    // ---------- attention ----------
    const float4* qf4 = (const float4*)(qf + (size_t)q * CDIM);
    const float4 qa = qf4[lane], qb = qf4[32 + lane];

    // QK^T: 25 groups of 4 rows (8 LDG.128 in flight)
    for (int gr = 0; gr < 25; gr++) {
        const int4 id = *(const int4*)&s_idx[w][gr * 4];
        const float4* k0 = (const float4*)(kf + (size_t)id.x * CDIM);
        const float4* k1 = (const float4*)(kf + (size_t)id.y * CDIM);
        const float4* k2 = (const float4*)(kf + (size_t)id.z * CDIM);
        const float4* k3 = (const float4*)(kf + (size_t)id.w * CDIM);
        float4 a0 = k0[lane], b0 = k0[32 + lane];
        float4 a1 = k1[lane], b1 = k1[32 + lane];
        float4 a2 = k2[lane], b2 = k2[32 + lane];
        float4 a3 = k3[lane], b3 = k3[32 + lane];
        float s0 = qa.x * a0.x, s1 = qa.x * a1.x, s2 = qa.x * a2.x, s3 = qa.x * a3.x;
        s0 = fmaf(qa.y, a0.y, s0); s1 = fmaf(qa.y, a1.y, s1); s2 = fmaf(qa.y, a2.y, s2); s3 = fmaf(qa.y, a3.y, s3);
        s0 = fmaf(qa.z, a0.z, s0); s1 = fmaf(qa.z, a1.z, s1); s2 = fmaf(qa.z, a2.z, s2); s3 = fmaf(qa.z, a3.z, s3);
        s0 = fmaf(qa.w, a0.w, s0); s1 = fmaf(qa.w, a1.w, s1); s2 = fmaf(qa.w, a2.w, s2); s3 = fmaf(qa.w, a3.w, s3);
        s0 = fmaf(qb.x, b0.x, s0); s1 = fmaf(qb.x, b1.x, s1); s2 = fmaf(qb.x, b2.x, s2); s3 = fmaf(qb.x, b3.x, s3);
        s0 = fmaf(qb.y, b0.y, s0); s1 = fmaf(qb.y, b1.y, s1); s2 = fmaf(qb.y, b2.y, s2); s3 = fmaf(qb.y, b3.y, s3);
        s0 = fmaf(qb.z, b0.z, s0); s1 = fmaf(qb.z, b1.z, s1); s2 = fmaf(qb.z, b2.z, s2); s3 = fmaf(qb.z, b3.z, s3);
        s0 = fmaf(qb.w, b0.w, s0); s1 = fmaf(qb.w, b1.w, s1); s2 = fmaf(qb.w, b2.w, s2); s3 = fmaf(qb.w, b3.w, s3);
#pragma unroll
        for (int o = 16; o; o >>= 1) {
            s0 += __shfl_xor_sync(FULLM, s0, o);
            s1 += __shfl_xor_sync(FULLM, s1, o);
            s2 += __shfl_xor_sync(FULLM, s2, o);
            s3 += __shfl_xor_sync(FULLM, s3, o);
        }
        if (lane == 0)
            *(float4*)&s_p[w][gr * 4] =
                make_float4(s0 * 0.0625f, s1 * 0.0625f, s2 * 0.0625f, s3 * 0.0625f);
    }
    __syncwarp();

    // softmax within the warp
    float l0 = s_p[w][lane], l1 = s_p[w][lane + 32], l2 = s_p[w][lane + 64];
    float l3 = (lane < 4) ? s_p[w][lane + 96] : -CUDART_INF_F;
    float mx = warp_max_f(fmaxf(fmaxf(l0, l1), fmaxf(l2, l3)));
    float e0 = __expf(l0 - mx), e1 = __expf(l1 - mx), e2 = __expf(l2 - mx);
    float e3 = (lane < 4) ? __expf(l3 - mx) : 0.f;
    float sm = warp_sum_f((e0 + e1) + (e2 + e3));
    s_p[w][lane] = e0; s_p[w][lane + 32] = e1; s_p[w][lane + 64] = e2;
    if (lane < 4) s_p[w][lane + 96] = e3;
    const float sc = 2.f / sm;   // res fully overwritten by x: y = 2x; fold 1/sum
    __syncwarp();

    // PV: 2 chains x 4 rows per group
    float4 A0 = make_float4(0.f, 0.f, 0.f, 0.f), B0 = A0, A1 = A0, B1 = A0;
    for (int gr = 0; gr < 25; gr++) {
        const int4 id = *(const int4*)&s_idx[w][gr * 4];
        const float4 p4 = *(const float4*)&s_p[w][gr * 4];
        const float4* v0 = (const float4*)(vf + (size_t)id.x * CDIM);
        const float4* v1 = (const float4*)(vf + (size_t)id.y * CDIM);
        const float4* v2 = (const float4*)(vf + (size_t)id.z * CDIM);
        const float4* v3 = (const float4*)(vf + (size_t)id.w * CDIM);
        float4 va0 = v0[lane], vb0 = v0[32 + lane];
        float4 va1 = v1[lane], vb1 = v1[32 + lane];
        float4 va2 = v2[lane], vb2 = v2[32 + lane];
        float4 va3 = v3[lane], vb3 = v3[32 + lane];
        A0.x = fmaf(p4.x, va0.x, A0.x); A0.y = fmaf(p4.x, va0.y, A0.y);
        A0.z = fmaf(p4.x, va0.z, A0.z); A0.w = fmaf(p4.x, va0.w, A0.w);
        B0.x = fmaf(p4.x, vb0.x, B0.x); B0.y = fmaf(p4.x, vb0.y, B0.y);
        B0.z = fmaf(p4.x, vb0.z, B0.z); B0.w = fmaf(p4.x, vb0.w, B0.w);
        A1.x = fmaf(p4.y, va1.x, A1.x); A1.y = fmaf(p4.y, va1.y, A1.y);
        A1.z = fmaf(p4.y, va1.z, A1.z); A1.w = fmaf(p4.y, va1.w, A1.w);
        B1.x = fmaf(p4.y, vb1.x, B1.x); B1.y = fmaf(p4.y, vb1.y, B1.y);
        B1.z = fmaf(p4.y, vb1.z, B1.z); B1.w = fmaf(p4.y, vb1.w, B1.w);
        A0.x = fmaf(p4.z, va2.x, A0.x); A0.y = fmaf(p4.z, va2.y, A0.y);
        A0.z = fmaf(p4.z, va2.z, A0.z); A0.w = fmaf(p4.z, va2.w, A0.w);
        B0.x = fmaf(p4.z, vb2.x, B0.x); B0.y = fmaf(p4.z, vb2.y, B0.y);
        B0.z = fmaf(p4.z, vb2.z, B0.z); B0.w = fmaf(p4.z, vb2.w, B0.w);
        A1.x = fmaf(p4.w, va3.x, A1.x); A1.y = fmaf(p4.w, va3.y, A1.y);
        A1.z = fmaf(p4.w, va3.z, A1.z); A1.w = fmaf(p4.w, va3.w, A1.w);
        B1.x = fmaf(p4.w, vb3.x, B1.x); B1.y = fmaf(p4.w, vb3.y, B1.y);
        B1.z = fmaf(p4.w, vb3.z, B1.z); B1.w = fmaf(p4.w, vb3.w, B1.w);
    }
    float4 A = make_float4((A0.x + A1.x) * sc, (A0.y + A1.y) * sc,
                           (A0.z + A1.z) * sc, (A0.w + A1.w) * sc);
    float4 B = make_float4((B0.x + B1.x) * sc, (B0.y + B1.y) * sc,
                           (B0.z + B1.z) * sc, (B0.w + B1.w) * sc);

    // LayerNorm within the warp
    float s = ((A.x + A.y) + (A.z + A.w)) + ((B.x + B.y) + (B.z + B.w));
    const float mean = warp_sum_f(s) * (1.f / CDIM);
    float dAx = A.x - mean, dAy = A.y - mean, dAz = A.z - mean, dAw = A.w - mean;
    float dBx = B.x - mean, dBy = B.y - mean, dBz = B.z - mean, dBw = B.w - mean;
    float s2 = ((dAx * dAx + dAy * dAy) + (dAz * dAz + dAw * dAw))
             + ((dBx * dBx + dBy * dBy) + (dBz * dBz + dBw * dBw));
    const float rstd = rsqrtf(warp_sum_f(s2) * (1.f / CDIM) + 1e-5f);

    const float4* g4 = (const float4*)gamma;
    const float4* b4 = (const float4*)beta;
    float4 ga = g4[lane], gb = g4[32 + lane];
    float4 ba = b4[lane], bb = b4[32 + lane];
    float4* o4 = (float4*)(out + (size_t)q * CDIM);
    o4[lane] = make_float4(fmaf(dAx * rstd, ga.x, ba.x),
                           fmaf(dAy * rstd, ga.y, ba.y),
                           fmaf(dAz * rstd, ga.z, ba.z),
                           fmaf(dAw * rstd, ga.w, ba.w));
    o4[32 + lane] = make_float4(fmaf(dBx * rstd, gb.x, bb.x),
                                fmaf(dBy * rstd, gb.y, bb.y),
                                fmaf(dBz * rstd, gb.z, bb.z),
                                fmaf(dBw * rstd, gb.w, bb.w));
}

// ---------------- launch ----------------
extern "C" void kernel_launch(void* const* d_in, const int* in_sizes, int n_in,
                              void* d_out, int out_size) {
    (void)in_sizes; (void)n_in; (void)out_size;
    const float* qf    = (const float*)d_in[1];
    const float* kf    = (const float*)d_in[2];
    const float* vf    = (const float*)d_in[3];
    const float* qpos  = (const float*)d_in[4];
    const float* kpos  = (const float*)d_in[5];
    const float* gamma = (const float*)d_in[6];
    const float* beta  = (const float*)d_in[7];

    knn_thr<<<NQ / 4, 128>>>(qpos, kpos);
    knn_scan<<<dim3(NQ / (WPB * QPW), NSPLIT), 32 * WPB>>>(qpos, kpos);
    attn_ln<<<NQ / AW, 32 * AW>>>(qf, kf, vf, gamma, beta, (float*)d_out);
}